// round 10
// baseline (speedup 1.0000x reference)
#include <cuda_runtime.h>
#include <cuda_bf16.h>
#include <math.h>

#define Bv_ 4
#define Tv_ 512
#define Mv_ 16
#define Dv_ 128
#define Pv_ 128
#define Hv_ 4
#define Ev_ 32
#define BT_ (Bv_*Tv_)      // 2048
#define BMH_ (Bv_*Mv_*Hv_) // 256

typedef unsigned int u32;
typedef unsigned short u16;

// ---------------------------------------------------------------------------
// Scratch planes (bf16 hi + lo residual)
// ---------------------------------------------------------------------------
__device__ __nv_bfloat16 g_QQh[BMH_ * Tv_ * 64];
__device__ __nv_bfloat16 g_QQl[BMH_ * Tv_ * 64];
__device__ __nv_bfloat16 g_KKh[BMH_ * Tv_ * 64];
__device__ __nv_bfloat16 g_KKl[BMH_ * Tv_ * 64];
__device__ __nv_bfloat16 g_Vh [BMH_ * Tv_ * Ev_];
__device__ __nv_bfloat16 g_Vl [BMH_ * Tv_ * Ev_];
// Prepped input / weight planes
__device__ __nv_bfloat16 g_Ih[BT_ * Mv_ * Dv_];
__device__ __nv_bfloat16 g_Il[BT_ * Mv_ * Dv_];
__device__ __nv_bfloat16 g_Ph[BT_ * Dv_];
__device__ __nv_bfloat16 g_Pl[BT_ * Dv_];
__device__ __nv_bfloat16 g_Wph[5 * Mv_ * Pv_ * Dv_];
__device__ __nv_bfloat16 g_Wpl[5 * Mv_ * Pv_ * Dv_];

// ---------------------------------------------------------------------------
__device__ __forceinline__ void mma_bf16(float& c0, float& c1, float& c2, float& c3,
                                         u32 a0, u32 a1, u32 a2, u32 a3,
                                         u32 b0, u32 b1) {
    asm volatile("mma.sync.aligned.m16n8k16.row.col.f32.bf16.bf16.f32 "
                 "{%0,%1,%2,%3},{%4,%5,%6,%7},{%8,%9},{%0,%1,%2,%3};"
                 : "+f"(c0), "+f"(c1), "+f"(c2), "+f"(c3)
                 : "r"(a0), "r"(a1), "r"(a2), "r"(a3), "r"(b0), "r"(b1));
}

__device__ __forceinline__ void split2(float x0, float x1, u32& h, u32& l) {
    __nv_bfloat162 bh = __floats2bfloat162_rn(x0, x1);
    float r0 = x0 - __bfloat162float(bh.x);
    float r1 = x1 - __bfloat162float(bh.y);
    __nv_bfloat162 bl = __floats2bfloat162_rn(r0, r1);
    h = *reinterpret_cast<u32*>(&bh);
    l = *reinterpret_cast<u32*>(&bl);
}

// ---------------------------------------------------------------------------
// Prep: convert inp/pos/W to bf16 hi/lo planes (float2 granularity).
// ---------------------------------------------------------------------------
#define NI2 (BT_*Mv_*Dv_/2)   // 2097152
#define NP2 (BT_*Dv_/2)       // 131072
#define NW2 (Mv_*Pv_*Dv_/2)   // 131072

__global__ void prep_kernel(const float* __restrict__ inp, const float* __restrict__ pos,
                            const float* __restrict__ Wq, const float* __restrict__ Wk,
                            const float* __restrict__ Wv, const float* __restrict__ Wqt,
                            const float* __restrict__ Wkt)
{
    int n = NI2 + NP2 + 5 * NW2;
    for (int i = blockIdx.x * blockDim.x + threadIdx.x; i < n; i += gridDim.x * blockDim.x) {
        const float2* src; u32 *dh, *dl; int off;
        if (i < NI2)            { src = (const float2*)inp; dh = (u32*)g_Ih; dl = (u32*)g_Il; off = i; }
        else if (i < NI2 + NP2) { src = (const float2*)pos; dh = (u32*)g_Ph; dl = (u32*)g_Pl; off = i - NI2; }
        else {
            int j = i - NI2 - NP2;
            int ws = j / NW2;
            const float* W = (ws == 0) ? Wq : (ws == 1) ? Wk : (ws == 2) ? Wv : (ws == 3) ? Wqt : Wkt;
            src = (const float2*)W; dh = (u32*)g_Wph + ws * NW2; dl = (u32*)g_Wpl + ws * NW2;
            off = j - ws * NW2;
        }
        float2 v = src[off];
        u32 h, l; split2(v.x, v.y, h, l);
        dh[off] = h; dl[off] = l;
    }
}

// ---------------------------------------------------------------------------
// Projection via mma.sync bf16 split-3. Block = 128 threads (4 warps).
// Staging = pure uint4 copies of prepped planes.
// ---------------------------------------------------------------------------
#define PJP_ 68

__global__ void __launch_bounds__(128) proj_kernel(
    const float* __restrict__ Bq,  const float* __restrict__ Bk,
    const float* __restrict__ Bvb, const float* __restrict__ Bqt,
    const float* __restrict__ Bkt, float scaleQ)
{
    extern __shared__ u32 smp[];
    u32* Xh = smp;
    u32* Xl = smp + 64 * PJP_;
    u32* Wh = smp + 2 * 64 * PJP_;
    u32* Wl = smp + 3 * 64 * PJP_;

    int m = blockIdx.x, row0 = blockIdx.y * 64, z = blockIdx.z;
    int tid = threadIdx.x;
    int w = tid >> 5, lane = tid & 31, g = lane >> 2, tl = lane & 3;

    // Stage X tile (once): 64 rows x 128 elems, hi/lo
    {
        int row = tid >> 1, hf = tid & 1;
        size_t eo = z ? ((size_t)(row0 + row) * Dv_ + hf * 64)
                      : (((size_t)(row0 + row) * Mv_ + m) * Dv_ + hf * 64);
        const uint4* sh = (const uint4*)((z ? g_Ph : g_Ih) + eo);
        const uint4* sl = (const uint4*)((z ? g_Pl : g_Il) + eo);
        uint4* dsth = (uint4*)(Xh + row * PJP_ + hf * 32);
        uint4* dstl = (uint4*)(Xl + row * PJP_ + hf * 32);
        #pragma unroll
        for (int j = 0; j < 8; ++j) { dsth[j] = sh[j]; dstl[j] = sl[j]; }
    }

    int nsel = z ? 2 : 3;
    for (int si = 0; si < nsel; ++si) {
        int dsel = z ? 3 + si : si;   // 0..4 == Wq,Wk,Wv,Wqt,Wkt (prep order)
        const float* Bi; float scale = 1.f;
        switch (dsel) {
            case 0:  Bi = Bq;  scale = scaleQ; break;
            case 1:  Bi = Bk;  break;
            case 2:  Bi = Bvb; break;
            case 3:  Bi = Bqt; scale = scaleQ; break;
            default: Bi = Bkt; break;
        }
        for (int ch = 0; ch < 2; ++ch) {
            __syncthreads();   // previous readers of Wh/Wl (and X stage) done
            {
                int row = tid >> 1, hf = tid & 1;
                size_t eo = (((size_t)dsel * Mv_ + m) * Pv_ + ch * 64 + row) * Dv_ + hf * 64;
                const uint4* sh = (const uint4*)(g_Wph + eo);
                const uint4* sl = (const uint4*)(g_Wpl + eo);
                uint4* dsth = (uint4*)(Wh + row * PJP_ + hf * 32);
                uint4* dstl = (uint4*)(Wl + row * PJP_ + hf * 32);
                #pragma unroll
                for (int j = 0; j < 8; ++j) { dsth[j] = sh[j]; dstl[j] = sl[j]; }
            }
            __syncthreads();

            float c[8][4];
            #pragma unroll
            for (int nt = 0; nt < 8; ++nt) { c[nt][0]=c[nt][1]=c[nt][2]=c[nt][3]=0.f; }

            const u32* xh0 = Xh + (16*w + g) * PJP_;
            const u32* xh1 = Xh + (16*w + g + 8) * PJP_;
            const u32* xl0 = Xl + (16*w + g) * PJP_;
            const u32* xl1 = Xl + (16*w + g + 8) * PJP_;
            #pragma unroll
            for (int kk = 0; kk < 8; ++kk) {
                int cu = 8 * kk + tl;
                u32 ah0 = xh0[cu], ah1 = xh1[cu], ah2 = xh0[cu+4], ah3 = xh1[cu+4];
                u32 al0 = xl0[cu], al1 = xl1[cu], al2 = xl0[cu+4], al3 = xl1[cu+4];
                #pragma unroll
                for (int nt = 0; nt < 8; ++nt) {
                    const u32* whp = Wh + (8*nt + g) * PJP_;
                    const u32* wlp = Wl + (8*nt + g) * PJP_;
                    u32 bh0 = whp[cu], bh1 = whp[cu+4];
                    u32 bl0 = wlp[cu], bl1 = wlp[cu+4];
                    mma_bf16(c[nt][0],c[nt][1],c[nt][2],c[nt][3], ah0,ah1,ah2,ah3, bh0,bh1);
                    mma_bf16(c[nt][0],c[nt][1],c[nt][2],c[nt][3], ah0,ah1,ah2,ah3, bl0,bl1);
                    mma_bf16(c[nt][0],c[nt][1],c[nt][2],c[nt][3], al0,al1,al2,al3, bh0,bh1);
                }
            }

            // Epilogue: bias, scale, bf16 split, scatter to head layout
            __nv_bfloat16 *dh, *dl; int pitch, eoff;
            switch (dsel) {
                case 0:  dh = g_QQh; dl = g_QQl; pitch = 64; eoff = 0;  break;
                case 1:  dh = g_KKh; dl = g_KKl; pitch = 64; eoff = 0;  break;
                case 2:  dh = g_Vh;  dl = g_Vl;  pitch = 32; eoff = 0;  break;
                case 3:  dh = g_QQh; dl = g_QQl; pitch = 64; eoff = 32; break;
                default: dh = g_KKh; dl = g_KKl; pitch = 64; eoff = 32; break;
            }
            int bt0 = row0 + 16*w + g;
            int bb0 = bt0 >> 9, t0 = bt0 & 511;
            int bt1 = bt0 + 8;
            int bb1 = bt1 >> 9, t1 = bt1 & 511;
            #pragma unroll
            for (int nt = 0; nt < 8; ++nt) {
                int col = ch * 64 + 8 * nt + 2 * tl;
                float b0v = Bi[m * Pv_ + col], b1v = Bi[m * Pv_ + col + 1];
                int hh = col >> 5, e = col & 31;
                float v00 = (c[nt][0] + b0v) * scale, v01 = (c[nt][1] + b1v) * scale;
                float v10 = (c[nt][2] + b0v) * scale, v11 = (c[nt][3] + b1v) * scale;
                u32 h00, l00, h10, l10;
                split2(v00, v01, h00, l00);
                split2(v10, v11, h10, l10);
                size_t base0 = ((size_t)((bb0 * Mv_ + m) * Hv_ + hh) * Tv_ + t0) * pitch + eoff + e;
                size_t base1 = ((size_t)((bb1 * Mv_ + m) * Hv_ + hh) * Tv_ + t1) * pitch + eoff + e;
                *(u32*)&dh[base0] = h00; *(u32*)&dl[base0] = l00;
                *(u32*)&dh[base1] = h10; *(u32*)&dl[base1] = l10;
            }
        }
    }
}

// ---------------------------------------------------------------------------
// Flash attention via mma.sync bf16 split-3. Block = 256 thr (8 warps),
// 128-query tile x 64-key tiles; warp w owns q rows 16w..16w+15.
// Causal warp-skip: tiles fully beyond a warp's rows skip compute (syncs are
// only at staging). V staged as packed s-pair u32, conflict-free.
// ---------------------------------------------------------------------------
#define ATP_ 36

__global__ void __launch_bounds__(256, 2) attn_kernel(
    const unsigned char* __restrict__ mask_raw, float* __restrict__ out)
{
    extern __shared__ u32 sma[];
    u32* Qh  = sma;                   // [128][36]
    u32* Ql  = Qh  + 128 * ATP_;
    u32* Kh  = Ql  + 128 * ATP_;      // [64][36]
    u32* Kl  = Kh  +  64 * ATP_;
    u32* Vth = Kl  +  64 * ATP_;      // [32 e][36] u32 s-pairs
    u32* Vtl = Vth +  32 * ATP_;

    int tid = threadIdx.x, w = tid >> 5, lane = tid & 31, g = lane >> 2, tl = lane & 3;
    int q0 = blockIdx.x * 128, bmh = blockIdx.y;
    int b = bmh >> 6, mh = bmh & 63, mm = mh >> 2, h = mh & 3;

    // Lengths inline (dtype-robust): mask[b,t,m] = t < len
    int len;
    {
        bool is_byte = (mask_raw[1] != 0);
        int p0, p1;
        if (is_byte) {
            p0 = (mask_raw[(size_t)(b * Tv_ + tid) * Mv_] != 0);
            p1 = (mask_raw[(size_t)(b * Tv_ + tid + 256) * Mv_] != 0);
        } else {
            const u32* mi = (const u32*)mask_raw;
            p0 = (mi[(size_t)(b * Tv_ + tid) * Mv_] != 0u);
            p1 = (mi[(size_t)(b * Tv_ + tid + 256) * Mv_] != 0u);
        }
        len = __syncthreads_count(p0) + __syncthreads_count(p1);
    }

    // Stage Q (hi/lo): 128 rows
    {
        int row = tid >> 1, hf = tid & 1;
        const uint4* sh = (const uint4*)(g_QQh + ((size_t)bmh * Tv_ + q0 + row) * 64 + hf * 32);
        const uint4* sl = (const uint4*)(g_QQl + ((size_t)bmh * Tv_ + q0 + row) * 64 + hf * 32);
        uint4* dhq = (uint4*)(Qh + row * ATP_ + hf * 16);
        uint4* dlq = (uint4*)(Ql + row * ATP_ + hf * 16);
        #pragma unroll
        for (int i = 0; i < 4; ++i) { dhq[i] = sh[i]; dlq[i] = sl[i]; }
    }

    float mx0 = -INFINITY, mx1 = -INFINITY, l0 = 0.f, l1 = 0.f;
    float o[4][4];
    #pragma unroll
    for (int i = 0; i < 4; ++i) { o[i][0]=o[i][1]=o[i][2]=o[i][3]=0.f; }

    int r0g = q0 + 16*w + g;
    int r1g = r0g + 8;
    int wmax = q0 + 16*w + 15;   // warp's max query row

    int smax = min(q0 + 128, len);
    for (int s0 = 0; s0 < smax; s0 += 64) {
        __syncthreads();   // prior tile's smem readers done (and Q staged, 1st iter)
        // Stage K (hi/lo): row = tid>>2, quarter = tid&3
        {
            int row = tid >> 2, q4 = tid & 3;
            const uint4* sh = (const uint4*)(g_KKh + ((size_t)bmh * Tv_ + s0 + row) * 64 + q4 * 16);
            const uint4* sl = (const uint4*)(g_KKl + ((size_t)bmh * Tv_ + s0 + row) * 64 + q4 * 16);
            uint4* dhk = (uint4*)(Kh + row * ATP_ + q4 * 8);
            uint4* dlk = (uint4*)(Kl + row * ATP_ + q4 * 8);
            dhk[0] = sh[0]; dhk[1] = sh[1];
            dlk[0] = sl[0]; dlk[1] = sl[1];
        }
        // Stage V as s-pair u32: warp -> (plane, e0), lane -> s2. Conflict-free.
        {
            int pl = w & 1, e0 = 8 * (w >> 1), s2 = lane;
            const __nv_bfloat16* Vsrc = pl ? g_Vl : g_Vh;
            u32* Vdst = pl ? Vtl : Vth;
            const u16* ra = (const u16*)(Vsrc + ((size_t)bmh * Tv_ + s0 + 2*s2) * Ev_ + e0);
            uint4 A = *(const uint4*)ra;
            uint4 Bx = *(const uint4*)(ra + Ev_);
            const u16* a  = (const u16*)&A;
            const u16* bb = (const u16*)&Bx;
            #pragma unroll
            for (int j = 0; j < 8; ++j)
                Vdst[(e0 + j) * ATP_ + s2] = (u32)a[j] | ((u32)bb[j] << 16);
        }
        __syncthreads();

        if (s0 > wmax) continue;   // tile fully beyond this warp's causal range

        // ---- QK mma ----
        float c[8][4];
        #pragma unroll
        for (int nt = 0; nt < 8; ++nt) { c[nt][0]=c[nt][1]=c[nt][2]=c[nt][3]=0.f; }

        const u32* qh0 = Qh + (16*w + g) * ATP_;
        const u32* qh1 = Qh + (16*w + g + 8) * ATP_;
        const u32* ql0 = Ql + (16*w + g) * ATP_;
        const u32* ql1 = Ql + (16*w + g + 8) * ATP_;
        #pragma unroll
        for (int kk = 0; kk < 4; ++kk) {
            int cu = 8 * kk + tl;
            u32 ah0 = qh0[cu], ah1 = qh1[cu], ah2 = qh0[cu+4], ah3 = qh1[cu+4];
            u32 al0 = ql0[cu], al1 = ql1[cu], al2 = ql0[cu+4], al3 = ql1[cu+4];
            #pragma unroll
            for (int nt = 0; nt < 8; ++nt) {
                const u32* khp = Kh + (8*nt + g) * ATP_;
                const u32* klp = Kl + (8*nt + g) * ATP_;
                u32 bh0 = khp[cu], bh1 = khp[cu+4];
                u32 bl0 = klp[cu], bl1 = klp[cu+4];
                mma_bf16(c[nt][0],c[nt][1],c[nt][2],c[nt][3], ah0,ah1,ah2,ah3, bh0,bh1);
                mma_bf16(c[nt][0],c[nt][1],c[nt][2],c[nt][3], ah0,ah1,ah2,ah3, bl0,bl1);
                mma_bf16(c[nt][0],c[nt][1],c[nt][2],c[nt][3], al0,al1,al2,al3, bh0,bh1);
            }
        }

        // ---- softmax in registers ----
        float rm0 = -1e30f, rm1 = -1e30f;
        #pragma unroll
        for (int nt = 0; nt < 8; ++nt) {
            int sg = s0 + 8 * nt + 2 * tl;
            if (!(sg     <= r0g && sg     < len)) c[nt][0] = -1e30f;
            if (!(sg + 1 <= r0g && sg + 1 < len)) c[nt][1] = -1e30f;
            if (!(sg     <= r1g && sg     < len)) c[nt][2] = -1e30f;
            if (!(sg + 1 <= r1g && sg + 1 < len)) c[nt][3] = -1e30f;
            rm0 = fmaxf(rm0, fmaxf(c[nt][0], c[nt][1]));
            rm1 = fmaxf(rm1, fmaxf(c[nt][2], c[nt][3]));
        }
        rm0 = fmaxf(rm0, __shfl_xor_sync(0xFFFFFFFFu, rm0, 1));
        rm0 = fmaxf(rm0, __shfl_xor_sync(0xFFFFFFFFu, rm0, 2));
        rm1 = fmaxf(rm1, __shfl_xor_sync(0xFFFFFFFFu, rm1, 1));
        rm1 = fmaxf(rm1, __shfl_xor_sync(0xFFFFFFFFu, rm1, 2));

        float mn0 = fmaxf(mx0, rm0), mn1 = fmaxf(mx1, rm1);
        float alpha0 = __expf(mx0 - mn0), alpha1 = __expf(mx1 - mn1);
        mx0 = mn0; mx1 = mn1;

        u32 ph0[8], ph1[8], pl0[8], pl1[8];
        float s0s = 0.f, s1s = 0.f;
        #pragma unroll
        for (int nt = 0; nt < 8; ++nt) {
            float p00 = __expf(c[nt][0] - mn0), p01 = __expf(c[nt][1] - mn0);
            float p10 = __expf(c[nt][2] - mn1), p11 = __expf(c[nt][3] - mn1);
            s0s += p00 + p01; s1s += p10 + p11;
            split2(p00, p01, ph0[nt], pl0[nt]);
            split2(p10, p11, ph1[nt], pl1[nt]);
        }
        s0s += __shfl_xor_sync(0xFFFFFFFFu, s0s, 1);
        s0s += __shfl_xor_sync(0xFFFFFFFFu, s0s, 2);
        s1s += __shfl_xor_sync(0xFFFFFFFFu, s1s, 1);
        s1s += __shfl_xor_sync(0xFFFFFFFFu, s1s, 2);
        l0 = l0 * alpha0 + s0s;
        l1 = l1 * alpha1 + s1s;
        #pragma unroll
        for (int nt = 0; nt < 4; ++nt) {
            o[nt][0] *= alpha0; o[nt][1] *= alpha0;
            o[nt][2] *= alpha1; o[nt][3] *= alpha1;
        }

        // ---- PV mma: A = P frags (reg reuse), B = Vt hi/lo ----
        #pragma unroll
        for (int nte = 0; nte < 4; ++nte) {
            const u32* vhp = Vth + (8*nte + g) * ATP_;
            const u32* vlp = Vtl + (8*nte + g) * ATP_;
            #pragma unroll
            for (int kk = 0; kk < 4; ++kk) {
                int cu = 8 * kk + tl;
                u32 bh0 = vhp[cu], bh1 = vhp[cu+4];
                u32 bl0 = vlp[cu], bl1 = vlp[cu+4];
                mma_bf16(o[nte][0],o[nte][1],o[nte][2],o[nte][3],
                         ph0[2*kk], ph1[2*kk], ph0[2*kk+1], ph1[2*kk+1], bh0, bh1);
                mma_bf16(o[nte][0],o[nte][1],o[nte][2],o[nte][3],
                         ph0[2*kk], ph1[2*kk], ph0[2*kk+1], ph1[2*kk+1], bl0, bl1);
                mma_bf16(o[nte][0],o[nte][1],o[nte][2],o[nte][3],
                         pl0[2*kk], pl1[2*kk], pl0[2*kk+1], pl1[2*kk+1], bh0, bh1);
            }
        }
    }

    // Epilogue
    float i0 = 1.f / l0, i1 = 1.f / l1;
    #pragma unroll
    for (int nte = 0; nte < 4; ++nte) {
        int e = 8 * nte + 2 * tl;
        float2 v0 = make_float2(o[nte][0] * i0, o[nte][1] * i0);
        float2 v1 = make_float2(o[nte][2] * i1, o[nte][3] * i1);
        *(float2*)&out[(((size_t)b * Tv_ + r0g) * Mv_ + mm) * Pv_ + h * Ev_ + e] = v0;
        *(float2*)&out[(((size_t)b * Tv_ + r1g) * Mv_ + mm) * Pv_ + h * Ev_ + e] = v1;
    }
}

// ---------------------------------------------------------------------------
extern "C" void kernel_launch(void* const* d_in, const int* in_sizes, int n_in,
                              void* d_out, int out_size)
{
    const float* inp  = (const float*)d_in[0];
    const float* pos  = (const float*)d_in[1];
    const unsigned char* mask = (const unsigned char*)d_in[2];
    const float* Wq  = (const float*)d_in[3];
    const float* Bq  = (const float*)d_in[4];
    const float* Wk  = (const float*)d_in[5];
    const float* Bk  = (const float*)d_in[6];
    const float* Wv  = (const float*)d_in[7];
    const float* Bv  = (const float*)d_in[8];
    const float* Wqt = (const float*)d_in[9];
    const float* Bqt = (const float*)d_in[10];
    const float* Wkt = (const float*)d_in[11];
    const float* Bkt = (const float*)d_in[12];
    float* out = (float*)d_out;

    const float SCALE = 0.08838834764831845f; // 1 / (2*sqrt(32))

    const int PROJ_SMEM = 4 * 64 * PJP_ * 4;                      // 69632 B
    const int ATTN_SMEM = (2*128 + 2*64 + 2*32) * ATP_ * 4;       // 64512 B
    cudaFuncSetAttribute(proj_kernel, cudaFuncAttributeMaxDynamicSharedMemorySize, PROJ_SMEM);
    cudaFuncSetAttribute(attn_kernel, cudaFuncAttributeMaxDynamicSharedMemorySize, ATTN_SMEM);

    prep_kernel<<<1024, 256>>>(inp, pos, Wq, Wk, Wv, Wqt, Wkt);

    dim3 pgrid(Mv_, BT_ / 64, 2);
    proj_kernel<<<pgrid, 128, PROJ_SMEM>>>(Bq, Bk, Bv, Bqt, Bkt, SCALE);

    dim3 agrid(Tv_ / 128, BMH_);
    attn_kernel<<<agrid, 256, ATTN_SMEM>>>(mask, out);
}

// round 13
// speedup vs baseline: 1.0529x; 1.0529x over previous
#include <cuda_runtime.h>
#include <cuda_bf16.h>
#include <math.h>

#define Bv_ 4
#define Tv_ 512
#define Mv_ 16
#define Dv_ 128
#define Pv_ 128
#define Hv_ 4
#define Ev_ 32
#define BT_ (Bv_*Tv_)      // 2048
#define BMH_ (Bv_*Mv_*Hv_) // 256

typedef unsigned int u32;
typedef unsigned short u16;

// ---------------------------------------------------------------------------
// Scratch planes: Q/K bf16 hi+lo (split-3 accuracy), V single fp16 plane.
// ---------------------------------------------------------------------------
__device__ __nv_bfloat16 g_QQh[BMH_ * Tv_ * 64];
__device__ __nv_bfloat16 g_QQl[BMH_ * Tv_ * 64];
__device__ __nv_bfloat16 g_KKh[BMH_ * Tv_ * 64];
__device__ __nv_bfloat16 g_KKl[BMH_ * Tv_ * 64];
__device__ u16           g_Vf [BMH_ * Tv_ * Ev_];   // fp16 bits
// Prepped weight planes (bf16 hi/lo)
__device__ __nv_bfloat16 g_Wph[5 * Mv_ * Pv_ * Dv_];
__device__ __nv_bfloat16 g_Wpl[5 * Mv_ * Pv_ * Dv_];

// ---------------------------------------------------------------------------
__device__ __forceinline__ void mma_bf16(float& c0, float& c1, float& c2, float& c3,
                                         u32 a0, u32 a1, u32 a2, u32 a3,
                                         u32 b0, u32 b1) {
    asm volatile("mma.sync.aligned.m16n8k16.row.col.f32.bf16.bf16.f32 "
                 "{%0,%1,%2,%3},{%4,%5,%6,%7},{%8,%9},{%0,%1,%2,%3};"
                 : "+f"(c0), "+f"(c1), "+f"(c2), "+f"(c3)
                 : "r"(a0), "r"(a1), "r"(a2), "r"(a3), "r"(b0), "r"(b1));
}
__device__ __forceinline__ void mma_f16(float& c0, float& c1, float& c2, float& c3,
                                        u32 a0, u32 a1, u32 a2, u32 a3,
                                        u32 b0, u32 b1) {
    asm volatile("mma.sync.aligned.m16n8k16.row.col.f32.f16.f16.f32 "
                 "{%0,%1,%2,%3},{%4,%5,%6,%7},{%8,%9},{%0,%1,%2,%3};"
                 : "+f"(c0), "+f"(c1), "+f"(c2), "+f"(c3)
                 : "r"(a0), "r"(a1), "r"(a2), "r"(a3), "r"(b0), "r"(b1));
}

// Split (x0,x1) into packed bf16 hi pair and bf16 residual pair. Low half = x0.
__device__ __forceinline__ void split2(float x0, float x1, u32& h, u32& l) {
    __nv_bfloat162 bh = __floats2bfloat162_rn(x0, x1);
    float r0 = x0 - __bfloat162float(bh.x);
    float r1 = x1 - __bfloat162float(bh.y);
    __nv_bfloat162 bl = __floats2bfloat162_rn(r0, r1);
    h = *reinterpret_cast<u32*>(&bh);
    l = *reinterpret_cast<u32*>(&bl);
}
// Pack two floats into f16x2 (lo = first arg).
__device__ __forceinline__ u32 cvt_f16x2(float lo, float hi) {
    u32 d; asm("cvt.rn.f16x2.f32 %0, %1, %2;" : "=r"(d) : "f"(hi), "f"(lo)); return d;
}

// ---------------------------------------------------------------------------
// Prep: convert the 5 weight tensors to bf16 hi/lo planes.
// ---------------------------------------------------------------------------
#define NW2 (Mv_*Pv_*Dv_/2)   // 131072 float2 per W

__global__ void prep_kernel(const float* __restrict__ Wq, const float* __restrict__ Wk,
                            const float* __restrict__ Wv, const float* __restrict__ Wqt,
                            const float* __restrict__ Wkt)
{
    int n = 5 * NW2;
    for (int i = blockIdx.x * blockDim.x + threadIdx.x; i < n; i += gridDim.x * blockDim.x) {
        int ws = i / NW2, off = i - ws * NW2;
        const float* W = (ws == 0) ? Wq : (ws == 1) ? Wk : (ws == 2) ? Wv : (ws == 3) ? Wqt : Wkt;
        float2 v = ((const float2*)W)[off];
        u32 h, l; split2(v.x, v.y, h, l);
        ((u32*)g_Wph)[i] = h;
        ((u32*)g_Wpl)[i] = l;
    }
}

// ---------------------------------------------------------------------------
// Projection via mma.sync bf16 split-3. Block = 128 threads (4 warps).
// grid (m=16, ytile=32, z=2). z=0: q,k,v from inp[m]; z=1: q_t,k_t from pos.
// X staged once per CTA with on-the-fly split2 from float gmem; W from
// prepped planes (uint4 copies). V epilogue writes single fp16 plane.
// ---------------------------------------------------------------------------
#define PJP_ 68

__global__ void __launch_bounds__(128) proj_kernel(
    const float* __restrict__ inp, const float* __restrict__ pos,
    const float* __restrict__ Bq,  const float* __restrict__ Bk,
    const float* __restrict__ Bvb, const float* __restrict__ Bqt,
    const float* __restrict__ Bkt, float scaleQ)
{
    extern __shared__ u32 smp[];
    u32* Xh = smp;
    u32* Xl = smp + 64 * PJP_;
    u32* Wh = smp + 2 * 64 * PJP_;
    u32* Wl = smp + 3 * 64 * PJP_;

    int m = blockIdx.x, row0 = blockIdx.y * 64, z = blockIdx.z;
    int tid = threadIdx.x;
    int w = tid >> 5, lane = tid & 31, g = lane >> 2, tl = lane & 3;

    // Stage X tile (once): split2 from float gmem
    {
        const float* Xb = z ? pos : inp + (size_t)m * Dv_;
        int stride = z ? Dv_ : Mv_ * Dv_;
        int row = tid >> 1, k0 = (tid & 1) * 64;
        const float4* src = (const float4*)&Xb[(size_t)(row0 + row) * stride + k0];
        u32* xh = Xh + row * PJP_ + k0 / 2;
        u32* xl = Xl + row * PJP_ + k0 / 2;
        #pragma unroll
        for (int j = 0; j < 16; ++j) {
            float4 v = src[j];
            u32 h0, l0, h1, l1;
            split2(v.x, v.y, h0, l0); split2(v.z, v.w, h1, l1);
            xh[2*j] = h0; xh[2*j+1] = h1; xl[2*j] = l0; xl[2*j+1] = l1;
        }
    }

    int nsel = z ? 2 : 3;
    for (int si = 0; si < nsel; ++si) {
        int dsel = z ? 3 + si : si;   // 0..4 == Wq,Wk,Wv,Wqt,Wkt (prep order)
        const float* Bi; float scale = 1.f;
        switch (dsel) {
            case 0:  Bi = Bq;  scale = scaleQ; break;
            case 1:  Bi = Bk;  break;
            case 2:  Bi = Bvb; break;
            case 3:  Bi = Bqt; scale = scaleQ; break;
            default: Bi = Bkt; break;
        }
        for (int ch = 0; ch < 2; ++ch) {
            __syncthreads();   // previous readers of Wh/Wl (and X stage) done
            {
                int row = tid >> 1, hf = tid & 1;
                size_t eo = (((size_t)dsel * Mv_ + m) * Pv_ + ch * 64 + row) * Dv_ + hf * 64;
                const uint4* sh = (const uint4*)(g_Wph + eo);
                const uint4* sl = (const uint4*)(g_Wpl + eo);
                uint4* dsth = (uint4*)(Wh + row * PJP_ + hf * 32);
                uint4* dstl = (uint4*)(Wl + row * PJP_ + hf * 32);
                #pragma unroll
                for (int j = 0; j < 8; ++j) { dsth[j] = sh[j]; dstl[j] = sl[j]; }
            }
            __syncthreads();

            float c[8][4];
            #pragma unroll
            for (int nt = 0; nt < 8; ++nt) { c[nt][0]=c[nt][1]=c[nt][2]=c[nt][3]=0.f; }

            const u32* xh0 = Xh + (16*w + g) * PJP_;
            const u32* xh1 = Xh + (16*w + g + 8) * PJP_;
            const u32* xl0 = Xl + (16*w + g) * PJP_;
            const u32* xl1 = Xl + (16*w + g + 8) * PJP_;
            #pragma unroll
            for (int kk = 0; kk < 8; ++kk) {
                int cu = 8 * kk + tl;
                u32 ah0 = xh0[cu], ah1 = xh1[cu], ah2 = xh0[cu+4], ah3 = xh1[cu+4];
                u32 al0 = xl0[cu], al1 = xl1[cu], al2 = xl0[cu+4], al3 = xl1[cu+4];
                #pragma unroll
                for (int nt = 0; nt < 8; ++nt) {
                    const u32* whp = Wh + (8*nt + g) * PJP_;
                    const u32* wlp = Wl + (8*nt + g) * PJP_;
                    u32 bh0 = whp[cu], bh1 = whp[cu+4];
                    u32 bl0 = wlp[cu], bl1 = wlp[cu+4];
                    mma_bf16(c[nt][0],c[nt][1],c[nt][2],c[nt][3], ah0,ah1,ah2,ah3, bh0,bh1);
                    mma_bf16(c[nt][0],c[nt][1],c[nt][2],c[nt][3], ah0,ah1,ah2,ah3, bl0,bl1);
                    mma_bf16(c[nt][0],c[nt][1],c[nt][2],c[nt][3], al0,al1,al2,al3, bh0,bh1);
                }
            }

            // Epilogue: bias, scale, split/convert, scatter to head layout
            __nv_bfloat16 *dh, *dl; int pitch, eoff;
            switch (dsel) {
                case 0:  dh = g_QQh; dl = g_QQl; pitch = 64; eoff = 0;  break;
                case 1:  dh = g_KKh; dl = g_KKl; pitch = 64; eoff = 0;  break;
                case 2:  dh = 0;     dl = 0;     pitch = 32; eoff = 0;  break;
                case 3:  dh = g_QQh; dl = g_QQl; pitch = 64; eoff = 32; break;
                default: dh = g_KKh; dl = g_KKl; pitch = 64; eoff = 32; break;
            }
            int bt0 = row0 + 16*w + g;
            int bb0 = bt0 >> 9, t0 = bt0 & 511;
            int bt1 = bt0 + 8;
            int bb1 = bt1 >> 9, t1 = bt1 & 511;
            #pragma unroll
            for (int nt = 0; nt < 8; ++nt) {
                int col = ch * 64 + 8 * nt + 2 * tl;
                float b0v = Bi[m * Pv_ + col], b1v = Bi[m * Pv_ + col + 1];
                int hh = col >> 5, e = col & 31;
                float v00 = (c[nt][0] + b0v) * scale, v01 = (c[nt][1] + b1v) * scale;
                float v10 = (c[nt][2] + b0v) * scale, v11 = (c[nt][3] + b1v) * scale;
                size_t base0 = ((size_t)((bb0 * Mv_ + m) * Hv_ + hh) * Tv_ + t0) * pitch + eoff + e;
                size_t base1 = ((size_t)((bb1 * Mv_ + m) * Hv_ + hh) * Tv_ + t1) * pitch + eoff + e;
                if (dsel == 2) {
                    *(u32*)&g_Vf[base0] = cvt_f16x2(v00, v01);
                    *(u32*)&g_Vf[base1] = cvt_f16x2(v10, v11);
                } else {
                    u32 h00, l00, h10, l10;
                    split2(v00, v01, h00, l00);
                    split2(v10, v11, h10, l10);
                    *(u32*)&dh[base0] = h00; *(u32*)&dl[base0] = l00;
                    *(u32*)&dh[base1] = h10; *(u32*)&dl[base1] = l10;
                }
            }
        }
    }
}

// ---------------------------------------------------------------------------
// Flash attention: QK = bf16 split-3 mma, PV = single fp16 mma.
// Block 256 thr (8 warps), 128-query tile x 64-key tiles, causal warp-skip.
// ---------------------------------------------------------------------------
#define ATP_ 36

__global__ void __launch_bounds__(256, 2) attn_kernel(
    const unsigned char* __restrict__ mask_raw, float* __restrict__ out)
{
    extern __shared__ u32 sma[];
    u32* Qh  = sma;                   // [128][36]
    u32* Ql  = Qh  + 128 * ATP_;
    u32* Kh  = Ql  + 128 * ATP_;      // [64][36]
    u32* Kl  = Kh  +  64 * ATP_;
    u32* Vth = Kl  +  64 * ATP_;      // [32 e][36] fp16 s-pairs

    int tid = threadIdx.x, w = tid >> 5, lane = tid & 31, g = lane >> 2, tl = lane & 3;
    int q0 = blockIdx.x * 128, bmh = blockIdx.y;
    int b = bmh >> 6, mh = bmh & 63, mm = mh >> 2, h = mh & 3;

    // Lengths inline (dtype-robust): mask[b,t,m] = t < len
    int len;
    {
        bool is_byte = (mask_raw[1] != 0);
        int p0, p1;
        if (is_byte) {
            p0 = (mask_raw[(size_t)(b * Tv_ + tid) * Mv_] != 0);
            p1 = (mask_raw[(size_t)(b * Tv_ + tid + 256) * Mv_] != 0);
        } else {
            const u32* mi = (const u32*)mask_raw;
            p0 = (mi[(size_t)(b * Tv_ + tid) * Mv_] != 0u);
            p1 = (mi[(size_t)(b * Tv_ + tid + 256) * Mv_] != 0u);
        }
        len = __syncthreads_count(p0) + __syncthreads_count(p1);
    }

    // Stage Q (hi/lo): 128 rows
    {
        int row = tid >> 1, hf = tid & 1;
        const uint4* sh = (const uint4*)(g_QQh + ((size_t)bmh * Tv_ + q0 + row) * 64 + hf * 32);
        const uint4* sl = (const uint4*)(g_QQl + ((size_t)bmh * Tv_ + q0 + row) * 64 + hf * 32);
        uint4* dhq = (uint4*)(Qh + row * ATP_ + hf * 16);
        uint4* dlq = (uint4*)(Ql + row * ATP_ + hf * 16);
        #pragma unroll
        for (int i = 0; i < 4; ++i) { dhq[i] = sh[i]; dlq[i] = sl[i]; }
    }

    float mx0 = -INFINITY, mx1 = -INFINITY, l0 = 0.f, l1 = 0.f;
    float o[4][4];
    #pragma unroll
    for (int i = 0; i < 4; ++i) { o[i][0]=o[i][1]=o[i][2]=o[i][3]=0.f; }

    int r0g = q0 + 16*w + g;
    int r1g = r0g + 8;
    int wmax = q0 + 16*w + 15;

    int smax = min(q0 + 128, len);
    for (int s0 = 0; s0 < smax; s0 += 64) {
        __syncthreads();
        // Stage K (hi/lo)
        {
            int row = tid >> 2, q4 = tid & 3;
            const uint4* sh = (const uint4*)(g_KKh + ((size_t)bmh * Tv_ + s0 + row) * 64 + q4 * 16);
            const uint4* sl = (const uint4*)(g_KKl + ((size_t)bmh * Tv_ + s0 + row) * 64 + q4 * 16);
            uint4* dhk = (uint4*)(Kh + row * ATP_ + q4 * 8);
            uint4* dlk = (uint4*)(Kl + row * ATP_ + q4 * 8);
            dhk[0] = sh[0]; dhk[1] = sh[1];
            dlk[0] = sl[0]; dlk[1] = sl[1];
        }
        // Stage V (fp16, single plane): warps 0..3, warp w -> e0 = 8w, lane -> s-pair
        if (w < 4) {
            int e0 = 8 * w, s2 = lane;
            const u16* ra = (const u16*)(g_Vf + ((size_t)bmh * Tv_ + s0 + 2*s2) * Ev_ + e0);
            uint4 A  = *(const uint4*)ra;          // 8 fp16, row s=2*s2
            uint4 Bx = *(const uint4*)(ra + Ev_);  // 8 fp16, row s=2*s2+1
            const u16* a  = (const u16*)&A;
            const u16* bb = (const u16*)&Bx;
            #pragma unroll
            for (int j = 0; j < 8; ++j)
                Vth[(e0 + j) * ATP_ + s2] = (u32)a[j] | ((u32)bb[j] << 16);
        }
        __syncthreads();

        if (s0 > wmax) continue;   // tile fully beyond this warp's causal range

        // ---- QK mma (bf16 split-3) ----
        float c[8][4];
        #pragma unroll
        for (int nt = 0; nt < 8; ++nt) { c[nt][0]=c[nt][1]=c[nt][2]=c[nt][3]=0.f; }

        const u32* qh0 = Qh + (16*w + g) * ATP_;
        const u32* qh1 = Qh + (16*w + g + 8) * ATP_;
        const u32* ql0 = Ql + (16*w + g) * ATP_;
        const u32* ql1 = Ql + (16*w + g + 8) * ATP_;
        #pragma unroll
        for (int kk = 0; kk < 4; ++kk) {
            int cu = 8 * kk + tl;
            u32 ah0 = qh0[cu], ah1 = qh1[cu], ah2 = qh0[cu+4], ah3 = qh1[cu+4];
            u32 al0 = ql0[cu], al1 = ql1[cu], al2 = ql0[cu+4], al3 = ql1[cu+4];
            #pragma unroll
            for (int nt = 0; nt < 8; ++nt) {
                const u32* khp = Kh + (8*nt + g) * ATP_;
                const u32* klp = Kl + (8*nt + g) * ATP_;
                u32 bh0 = khp[cu], bh1 = khp[cu+4];
                u32 bl0 = klp[cu], bl1 = klp[cu+4];
                mma_bf16(c[nt][0],c[nt][1],c[nt][2],c[nt][3], ah0,ah1,ah2,ah3, bh0,bh1);
                mma_bf16(c[nt][0],c[nt][1],c[nt][2],c[nt][3], ah0,ah1,ah2,ah3, bl0,bl1);
                mma_bf16(c[nt][0],c[nt][1],c[nt][2],c[nt][3], al0,al1,al2,al3, bh0,bh1);
            }
        }

        // ---- softmax in registers ----
        float rm0 = -1e30f, rm1 = -1e30f;
        #pragma unroll
        for (int nt = 0; nt < 8; ++nt) {
            int sg = s0 + 8 * nt + 2 * tl;
            if (!(sg     <= r0g && sg     < len)) c[nt][0] = -1e30f;
            if (!(sg + 1 <= r0g && sg + 1 < len)) c[nt][1] = -1e30f;
            if (!(sg     <= r1g && sg     < len)) c[nt][2] = -1e30f;
            if (!(sg + 1 <= r1g && sg + 1 < len)) c[nt][3] = -1e30f;
            rm0 = fmaxf(rm0, fmaxf(c[nt][0], c[nt][1]));
            rm1 = fmaxf(rm1, fmaxf(c[nt][2], c[nt][3]));
        }
        rm0 = fmaxf(rm0, __shfl_xor_sync(0xFFFFFFFFu, rm0, 1));
        rm0 = fmaxf(rm0, __shfl_xor_sync(0xFFFFFFFFu, rm0, 2));
        rm1 = fmaxf(rm1, __shfl_xor_sync(0xFFFFFFFFu, rm1, 1));
        rm1 = fmaxf(rm1, __shfl_xor_sync(0xFFFFFFFFu, rm1, 2));

        float mn0 = fmaxf(mx0, rm0), mn1 = fmaxf(mx1, rm1);
        float alpha0 = __expf(mx0 - mn0), alpha1 = __expf(mx1 - mn1);
        mx0 = mn0; mx1 = mn1;

        u32 ph0[8], ph1[8];
        float s0s = 0.f, s1s = 0.f;
        #pragma unroll
        for (int nt = 0; nt < 8; ++nt) {
            float p00 = __expf(c[nt][0] - mn0), p01 = __expf(c[nt][1] - mn0);
            float p10 = __expf(c[nt][2] - mn1), p11 = __expf(c[nt][3] - mn1);
            s0s += p00 + p01; s1s += p10 + p11;
            ph0[nt] = cvt_f16x2(p00, p01);
            ph1[nt] = cvt_f16x2(p10, p11);
        }
        s0s += __shfl_xor_sync(0xFFFFFFFFu, s0s, 1);
        s0s += __shfl_xor_sync(0xFFFFFFFFu, s0s, 2);
        s1s += __shfl_xor_sync(0xFFFFFFFFu, s1s, 1);
        s1s += __shfl_xor_sync(0xFFFFFFFFu, s1s, 2);
        l0 = l0 * alpha0 + s0s;
        l1 = l1 * alpha1 + s1s;
        #pragma unroll
        for (int nt = 0; nt < 4; ++nt) {
            o[nt][0] *= alpha0; o[nt][1] *= alpha0;
            o[nt][2] *= alpha1; o[nt][3] *= alpha1;
        }

        // ---- PV mma: single fp16 per (nte,kk) ----
        #pragma unroll
        for (int nte = 0; nte < 4; ++nte) {
            const u32* vhp = Vth + (8*nte + g) * ATP_;
            #pragma unroll
            for (int kk = 0; kk < 4; ++kk) {
                int cu = 8 * kk + tl;
                u32 bh0 = vhp[cu], bh1 = vhp[cu+4];
                mma_f16(o[nte][0],o[nte][1],o[nte][2],o[nte][3],
                        ph0[2*kk], ph1[2*kk], ph0[2*kk+1], ph1[2*kk+1], bh0, bh1);
            }
        }
    }

    // Epilogue
    float i0 = 1.f / l0, i1 = 1.f / l1;
    #pragma unroll
    for (int nte = 0; nte < 4; ++nte) {
        int e = 8 * nte + 2 * tl;
        float2 v0 = make_float2(o[nte][0] * i0, o[nte][1] * i0);
        float2 v1 = make_float2(o[nte][2] * i1, o[nte][3] * i1);
        *(float2*)&out[(((size_t)b * Tv_ + r0g) * Mv_ + mm) * Pv_ + h * Ev_ + e] = v0;
        *(float2*)&out[(((size_t)b * Tv_ + r1g) * Mv_ + mm) * Pv_ + h * Ev_ + e] = v1;
    }
}

// ---------------------------------------------------------------------------
extern "C" void kernel_launch(void* const* d_in, const int* in_sizes, int n_in,
                              void* d_out, int out_size)
{
    const float* inp  = (const float*)d_in[0];
    const float* pos  = (const float*)d_in[1];
    const unsigned char* mask = (const unsigned char*)d_in[2];
    const float* Wq  = (const float*)d_in[3];
    const float* Bq  = (const float*)d_in[4];
    const float* Wk  = (const float*)d_in[5];
    const float* Bk  = (const float*)d_in[6];
    const float* Wv  = (const float*)d_in[7];
    const float* Bv  = (const float*)d_in[8];
    const float* Wqt = (const float*)d_in[9];
    const float* Bqt = (const float*)d_in[10];
    const float* Wkt = (const float*)d_in[11];
    const float* Bkt = (const float*)d_in[12];
    float* out = (float*)d_out;

    const float SCALE = 0.08838834764831845f; // 1 / (2*sqrt(32))

    const int PROJ_SMEM = 4 * 64 * PJP_ * 4;                  // 69632 B
    const int ATTN_SMEM = (2*128 + 2*64 + 32) * ATP_ * 4;     // 59904 B
    cudaFuncSetAttribute(proj_kernel, cudaFuncAttributeMaxDynamicSharedMemorySize, PROJ_SMEM);
    cudaFuncSetAttribute(attn_kernel, cudaFuncAttributeMaxDynamicSharedMemorySize, ATTN_SMEM);

    prep_kernel<<<512, 256>>>(Wq, Wk, Wv, Wqt, Wkt);

    dim3 pgrid(Mv_, BT_ / 64, 2);
    proj_kernel<<<pgrid, 128, PROJ_SMEM>>>(inp, pos, Bq, Bk, Bv, Bqt, Bkt, SCALE);

    dim3 agrid(Tv_ / 128, BMH_);
    attn_kernel<<<agrid, 256, ATTN_SMEM>>>(mask, out);
}

// round 14
// speedup vs baseline: 1.0960x; 1.0409x over previous
#include <cuda_runtime.h>
#include <cuda_bf16.h>
#include <cuda_fp16.h>
#include <math.h>

#define Bv_ 4
#define Tv_ 512
#define Mv_ 16
#define Dv_ 128
#define Pv_ 128
#define Hv_ 4
#define Ev_ 32
#define BT_ (Bv_*Tv_)      // 2048
#define BMH_ (Bv_*Mv_*Hv_) // 256

typedef unsigned int u32;
typedef unsigned short u16;

// ---------------------------------------------------------------------------
// Scratch: Q fp16 hi+lo (split-2, ~2^-22), K single fp16, V single fp16.
// ---------------------------------------------------------------------------
__device__ u16 g_Qhf[BMH_ * Tv_ * 64];
__device__ u16 g_Qlf[BMH_ * Tv_ * 64];
__device__ u16 g_Kf [BMH_ * Tv_ * 64];
__device__ u16 g_Vf [BMH_ * Tv_ * Ev_];
// Prepped weight planes (bf16 hi/lo) for split-3 projection
__device__ __nv_bfloat16 g_Wph[5 * Mv_ * Pv_ * Dv_];
__device__ __nv_bfloat16 g_Wpl[5 * Mv_ * Pv_ * Dv_];

// ---------------------------------------------------------------------------
__device__ __forceinline__ void mma_bf16(float& c0, float& c1, float& c2, float& c3,
                                         u32 a0, u32 a1, u32 a2, u32 a3,
                                         u32 b0, u32 b1) {
    asm volatile("mma.sync.aligned.m16n8k16.row.col.f32.bf16.bf16.f32 "
                 "{%0,%1,%2,%3},{%4,%5,%6,%7},{%8,%9},{%0,%1,%2,%3};"
                 : "+f"(c0), "+f"(c1), "+f"(c2), "+f"(c3)
                 : "r"(a0), "r"(a1), "r"(a2), "r"(a3), "r"(b0), "r"(b1));
}
__device__ __forceinline__ void mma_f16(float& c0, float& c1, float& c2, float& c3,
                                        u32 a0, u32 a1, u32 a2, u32 a3,
                                        u32 b0, u32 b1) {
    asm volatile("mma.sync.aligned.m16n8k16.row.col.f32.f16.f16.f32 "
                 "{%0,%1,%2,%3},{%4,%5,%6,%7},{%8,%9},{%0,%1,%2,%3};"
                 : "+f"(c0), "+f"(c1), "+f"(c2), "+f"(c3)
                 : "r"(a0), "r"(a1), "r"(a2), "r"(a3), "r"(b0), "r"(b1));
}

// bf16 hi + bf16 residual (for weight prep / proj GEMM)
__device__ __forceinline__ void split2(float x0, float x1, u32& h, u32& l) {
    __nv_bfloat162 bh = __floats2bfloat162_rn(x0, x1);
    float r0 = x0 - __bfloat162float(bh.x);
    float r1 = x1 - __bfloat162float(bh.y);
    __nv_bfloat162 bl = __floats2bfloat162_rn(r0, r1);
    h = *reinterpret_cast<u32*>(&bh);
    l = *reinterpret_cast<u32*>(&bl);
}
// fp16 hi + fp16 residual pair (for Q)
__device__ __forceinline__ void split2h(float x0, float x1, u32& h, u32& l) {
    __half h0 = __float2half_rn(x0), h1 = __float2half_rn(x1);
    float r0 = x0 - __half2float(h0), r1 = x1 - __half2float(h1);
    __half l0 = __float2half_rn(r0), l1 = __float2half_rn(r1);
    h = (u32)__half_as_ushort(h0) | ((u32)__half_as_ushort(h1) << 16);
    l = (u32)__half_as_ushort(l0) | ((u32)__half_as_ushort(l1) << 16);
}
// Pack two floats into f16x2 (lo = first arg).
__device__ __forceinline__ u32 cvt_f16x2(float lo, float hi) {
    u32 d; asm("cvt.rn.f16x2.f32 %0, %1, %2;" : "=r"(d) : "f"(hi), "f"(lo)); return d;
}

// ---------------------------------------------------------------------------
// Prep: convert the 5 weight tensors to bf16 hi/lo planes.
// ---------------------------------------------------------------------------
#define NW2 (Mv_*Pv_*Dv_/2)

__global__ void prep_kernel(const float* __restrict__ Wq, const float* __restrict__ Wk,
                            const float* __restrict__ Wv, const float* __restrict__ Wqt,
                            const float* __restrict__ Wkt)
{
    int n = 5 * NW2;
    for (int i = blockIdx.x * blockDim.x + threadIdx.x; i < n; i += gridDim.x * blockDim.x) {
        int ws = i / NW2, off = i - ws * NW2;
        const float* W = (ws == 0) ? Wq : (ws == 1) ? Wk : (ws == 2) ? Wv : (ws == 3) ? Wqt : Wkt;
        float2 v = ((const float2*)W)[off];
        u32 h, l; split2(v.x, v.y, h, l);
        ((u32*)g_Wph)[i] = h;
        ((u32*)g_Wpl)[i] = l;
    }
}

// ---------------------------------------------------------------------------
// Projection via mma.sync bf16 split-3. Block = 128 threads (4 warps).
// grid (m=16, ytile=32, z=2). Epilogue writes fp16 layouts for attention.
// ---------------------------------------------------------------------------
#define PJP_ 68

__global__ void __launch_bounds__(128) proj_kernel(
    const float* __restrict__ inp, const float* __restrict__ pos,
    const float* __restrict__ Bq,  const float* __restrict__ Bk,
    const float* __restrict__ Bvb, const float* __restrict__ Bqt,
    const float* __restrict__ Bkt, float scaleQ)
{
    extern __shared__ u32 smp[];
    u32* Xh = smp;
    u32* Xl = smp + 64 * PJP_;
    u32* Wh = smp + 2 * 64 * PJP_;
    u32* Wl = smp + 3 * 64 * PJP_;

    int m = blockIdx.x, row0 = blockIdx.y * 64, z = blockIdx.z;
    int tid = threadIdx.x;
    int w = tid >> 5, lane = tid & 31, g = lane >> 2, tl = lane & 3;

    // Stage X tile (once): split2 from float gmem
    {
        const float* Xb = z ? pos : inp + (size_t)m * Dv_;
        int stride = z ? Dv_ : Mv_ * Dv_;
        int row = tid >> 1, k0 = (tid & 1) * 64;
        const float4* src = (const float4*)&Xb[(size_t)(row0 + row) * stride + k0];
        u32* xh = Xh + row * PJP_ + k0 / 2;
        u32* xl = Xl + row * PJP_ + k0 / 2;
        #pragma unroll
        for (int j = 0; j < 16; ++j) {
            float4 v = src[j];
            u32 h0, l0, h1, l1;
            split2(v.x, v.y, h0, l0); split2(v.z, v.w, h1, l1);
            xh[2*j] = h0; xh[2*j+1] = h1; xl[2*j] = l0; xl[2*j+1] = l1;
        }
    }

    int nsel = z ? 2 : 3;
    for (int si = 0; si < nsel; ++si) {
        int dsel = z ? 3 + si : si;   // 0..4 == Wq,Wk,Wv,Wqt,Wkt
        const float* Bi; float scale = 1.f;
        switch (dsel) {
            case 0:  Bi = Bq;  scale = scaleQ; break;
            case 1:  Bi = Bk;  break;
            case 2:  Bi = Bvb; break;
            case 3:  Bi = Bqt; scale = scaleQ; break;
            default: Bi = Bkt; break;
        }
        for (int ch = 0; ch < 2; ++ch) {
            __syncthreads();   // previous readers of Wh/Wl (and X stage) done
            {
                int row = tid >> 1, hf = tid & 1;
                size_t eo = (((size_t)dsel * Mv_ + m) * Pv_ + ch * 64 + row) * Dv_ + hf * 64;
                const uint4* sh = (const uint4*)(g_Wph + eo);
                const uint4* sl = (const uint4*)(g_Wpl + eo);
                uint4* dsth = (uint4*)(Wh + row * PJP_ + hf * 32);
                uint4* dstl = (uint4*)(Wl + row * PJP_ + hf * 32);
                #pragma unroll
                for (int j = 0; j < 8; ++j) { dsth[j] = sh[j]; dstl[j] = sl[j]; }
            }
            __syncthreads();

            float c[8][4];
            #pragma unroll
            for (int nt = 0; nt < 8; ++nt) { c[nt][0]=c[nt][1]=c[nt][2]=c[nt][3]=0.f; }

            const u32* xh0 = Xh + (16*w + g) * PJP_;
            const u32* xh1 = Xh + (16*w + g + 8) * PJP_;
            const u32* xl0 = Xl + (16*w + g) * PJP_;
            const u32* xl1 = Xl + (16*w + g + 8) * PJP_;
            #pragma unroll
            for (int kk = 0; kk < 8; ++kk) {
                int cu = 8 * kk + tl;
                u32 ah0 = xh0[cu], ah1 = xh1[cu], ah2 = xh0[cu+4], ah3 = xh1[cu+4];
                u32 al0 = xl0[cu], al1 = xl1[cu], al2 = xl0[cu+4], al3 = xl1[cu+4];
                #pragma unroll
                for (int nt = 0; nt < 8; ++nt) {
                    const u32* whp = Wh + (8*nt + g) * PJP_;
                    const u32* wlp = Wl + (8*nt + g) * PJP_;
                    u32 bh0 = whp[cu], bh1 = whp[cu+4];
                    u32 bl0 = wlp[cu], bl1 = wlp[cu+4];
                    mma_bf16(c[nt][0],c[nt][1],c[nt][2],c[nt][3], ah0,ah1,ah2,ah3, bh0,bh1);
                    mma_bf16(c[nt][0],c[nt][1],c[nt][2],c[nt][3], ah0,ah1,ah2,ah3, bl0,bl1);
                    mma_bf16(c[nt][0],c[nt][1],c[nt][2],c[nt][3], al0,al1,al2,al3, bh0,bh1);
                }
            }

            // Epilogue: bias, scale, convert to attn layouts
            int pitch = (dsel == 2) ? 32 : 64;
            int eoff  = (dsel >= 3) ? 32 : 0;
            int bt0 = row0 + 16*w + g;
            int bb0 = bt0 >> 9, t0 = bt0 & 511;
            int bt1 = bt0 + 8;
            int bb1 = bt1 >> 9, t1 = bt1 & 511;
            #pragma unroll
            for (int nt = 0; nt < 8; ++nt) {
                int col = ch * 64 + 8 * nt + 2 * tl;
                float b0v = Bi[m * Pv_ + col], b1v = Bi[m * Pv_ + col + 1];
                int hh = col >> 5, e = col & 31;
                float v00 = (c[nt][0] + b0v) * scale, v01 = (c[nt][1] + b1v) * scale;
                float v10 = (c[nt][2] + b0v) * scale, v11 = (c[nt][3] + b1v) * scale;
                size_t base0 = ((size_t)((bb0 * Mv_ + m) * Hv_ + hh) * Tv_ + t0) * pitch + eoff + e;
                size_t base1 = ((size_t)((bb1 * Mv_ + m) * Hv_ + hh) * Tv_ + t1) * pitch + eoff + e;
                if (dsel == 2) {                       // V: single fp16
                    *(u32*)&g_Vf[base0] = cvt_f16x2(v00, v01);
                    *(u32*)&g_Vf[base1] = cvt_f16x2(v10, v11);
                } else if (dsel == 0 || dsel == 3) {   // Q: fp16 hi + residual
                    u32 h0, l0, h1, l1;
                    split2h(v00, v01, h0, l0);
                    split2h(v10, v11, h1, l1);
                    *(u32*)&g_Qhf[base0] = h0; *(u32*)&g_Qlf[base0] = l0;
                    *(u32*)&g_Qhf[base1] = h1; *(u32*)&g_Qlf[base1] = l1;
                } else {                               // K: single fp16
                    *(u32*)&g_Kf[base0] = cvt_f16x2(v00, v01);
                    *(u32*)&g_Kf[base1] = cvt_f16x2(v10, v11);
                }
            }
        }
    }
}

// ---------------------------------------------------------------------------
// Flash attention: QK = fp16 2-mma (Qhi,Qlo x Kf), PV = single fp16 mma.
// Block 256 thr (8 warps), 128-query tile x 64-key tiles, causal warp-skip
// at tile AND nt-chunk granularity.
// ---------------------------------------------------------------------------
#define ATP_ 36

__global__ void __launch_bounds__(256, 2) attn_kernel(
    const unsigned char* __restrict__ mask_raw, float* __restrict__ out)
{
    extern __shared__ u32 sma[];
    u32* Qh  = sma;                   // [128][36]
    u32* Ql  = Qh  + 128 * ATP_;
    u32* Kf  = Ql  + 128 * ATP_;      // [64][36]
    u32* Vth = Kf  +  64 * ATP_;      // [32 e][36] fp16 s-pairs

    int tid = threadIdx.x, w = tid >> 5, lane = tid & 31, g = lane >> 2, tl = lane & 3;
    int q0 = blockIdx.x * 128, bmh = blockIdx.y;
    int b = bmh >> 6, mh = bmh & 63, mm = mh >> 2, h = mh & 3;

    // Lengths inline (dtype-robust): mask[b,t,m] = t < len
    int len;
    {
        bool is_byte = (mask_raw[1] != 0);
        int p0, p1;
        if (is_byte) {
            p0 = (mask_raw[(size_t)(b * Tv_ + tid) * Mv_] != 0);
            p1 = (mask_raw[(size_t)(b * Tv_ + tid + 256) * Mv_] != 0);
        } else {
            const u32* mi = (const u32*)mask_raw;
            p0 = (mi[(size_t)(b * Tv_ + tid) * Mv_] != 0u);
            p1 = (mi[(size_t)(b * Tv_ + tid + 256) * Mv_] != 0u);
        }
        len = __syncthreads_count(p0) + __syncthreads_count(p1);
    }

    // Stage Q (hi/lo fp16): 128 rows
    {
        int row = tid >> 1, hf = tid & 1;
        const uint4* sh = (const uint4*)(g_Qhf + ((size_t)bmh * Tv_ + q0 + row) * 64 + hf * 32);
        const uint4* sl = (const uint4*)(g_Qlf + ((size_t)bmh * Tv_ + q0 + row) * 64 + hf * 32);
        uint4* dhq = (uint4*)(Qh + row * ATP_ + hf * 16);
        uint4* dlq = (uint4*)(Ql + row * ATP_ + hf * 16);
        #pragma unroll
        for (int i = 0; i < 4; ++i) { dhq[i] = sh[i]; dlq[i] = sl[i]; }
    }

    float mx0 = -INFINITY, mx1 = -INFINITY, l0 = 0.f, l1 = 0.f;
    float o[4][4];
    #pragma unroll
    for (int i = 0; i < 4; ++i) { o[i][0]=o[i][1]=o[i][2]=o[i][3]=0.f; }

    int r0g = q0 + 16*w + g;
    int r1g = r0g + 8;
    int wmax = q0 + 16*w + 15;

    int smax = min(q0 + 128, len);
    for (int s0 = 0; s0 < smax; s0 += 64) {
        __syncthreads();
        // Stage K (single fp16 plane)
        {
            int row = tid >> 2, q4 = tid & 3;
            const uint4* sk = (const uint4*)(g_Kf + ((size_t)bmh * Tv_ + s0 + row) * 64 + q4 * 16);
            uint4* dk = (uint4*)(Kf + row * ATP_ + q4 * 8);
            dk[0] = sk[0]; dk[1] = sk[1];
        }
        // Stage V (fp16): warps 0..3, warp w -> e0 = 8w, lane -> s-pair
        if (w < 4) {
            int e0 = 8 * w, s2 = lane;
            const u16* ra = (const u16*)(g_Vf + ((size_t)bmh * Tv_ + s0 + 2*s2) * Ev_ + e0);
            uint4 A  = *(const uint4*)ra;
            uint4 Bx = *(const uint4*)(ra + Ev_);
            const u16* a  = (const u16*)&A;
            const u16* bb = (const u16*)&Bx;
            #pragma unroll
            for (int j = 0; j < 8; ++j)
                Vth[(e0 + j) * ATP_ + s2] = (u32)a[j] | ((u32)bb[j] << 16);
        }
        __syncthreads();

        if (s0 > wmax) continue;   // tile fully beyond this warp's causal range

        // ---- QK mma (fp16 2-term) with nt-chunk causal skip ----
        float c[8][4];
        #pragma unroll
        for (int nt = 0; nt < 8; ++nt) { c[nt][0]=c[nt][1]=c[nt][2]=c[nt][3]=0.f; }

        const u32* qh0 = Qh + (16*w + g) * ATP_;
        const u32* qh1 = Qh + (16*w + g + 8) * ATP_;
        const u32* ql0 = Ql + (16*w + g) * ATP_;
        const u32* ql1 = Ql + (16*w + g + 8) * ATP_;
        #pragma unroll
        for (int kk = 0; kk < 4; ++kk) {
            int cu = 8 * kk + tl;
            u32 ah0 = qh0[cu], ah1 = qh1[cu], ah2 = qh0[cu+4], ah3 = qh1[cu+4];
            u32 al0 = ql0[cu], al1 = ql1[cu], al2 = ql0[cu+4], al3 = ql1[cu+4];
            #pragma unroll
            for (int nt = 0; nt < 8; ++nt) {
                if (s0 + 8 * nt <= wmax) {    // warp-uniform causal chunk skip
                    const u32* kp = Kf + (8*nt + g) * ATP_;
                    u32 b0 = kp[cu], b1 = kp[cu+4];
                    mma_f16(c[nt][0],c[nt][1],c[nt][2],c[nt][3], ah0,ah1,ah2,ah3, b0,b1);
                    mma_f16(c[nt][0],c[nt][1],c[nt][2],c[nt][3], al0,al1,al2,al3, b0,b1);
                }
            }
        }

        // ---- softmax in registers ----
        float rm0 = -1e30f, rm1 = -1e30f;
        #pragma unroll
        for (int nt = 0; nt < 8; ++nt) {
            int sg = s0 + 8 * nt + 2 * tl;
            if (!(sg     <= r0g && sg     < len)) c[nt][0] = -1e30f;
            if (!(sg + 1 <= r0g && sg + 1 < len)) c[nt][1] = -1e30f;
            if (!(sg     <= r1g && sg     < len)) c[nt][2] = -1e30f;
            if (!(sg + 1 <= r1g && sg + 1 < len)) c[nt][3] = -1e30f;
            rm0 = fmaxf(rm0, fmaxf(c[nt][0], c[nt][1]));
            rm1 = fmaxf(rm1, fmaxf(c[nt][2], c[nt][3]));
        }
        rm0 = fmaxf(rm0, __shfl_xor_sync(0xFFFFFFFFu, rm0, 1));
        rm0 = fmaxf(rm0, __shfl_xor_sync(0xFFFFFFFFu, rm0, 2));
        rm1 = fmaxf(rm1, __shfl_xor_sync(0xFFFFFFFFu, rm1, 1));
        rm1 = fmaxf(rm1, __shfl_xor_sync(0xFFFFFFFFu, rm1, 2));

        float mn0 = fmaxf(mx0, rm0), mn1 = fmaxf(mx1, rm1);
        float alpha0 = __expf(mx0 - mn0), alpha1 = __expf(mx1 - mn1);
        mx0 = mn0; mx1 = mn1;

        u32 ph0[8], ph1[8];
        float s0s = 0.f, s1s = 0.f;
        #pragma unroll
        for (int nt = 0; nt < 8; ++nt) {
            float p00 = __expf(c[nt][0] - mn0), p01 = __expf(c[nt][1] - mn0);
            float p10 = __expf(c[nt][2] - mn1), p11 = __expf(c[nt][3] - mn1);
            s0s += p00 + p01; s1s += p10 + p11;
            ph0[nt] = cvt_f16x2(p00, p01);
            ph1[nt] = cvt_f16x2(p10, p11);
        }
        s0s += __shfl_xor_sync(0xFFFFFFFFu, s0s, 1);
        s0s += __shfl_xor_sync(0xFFFFFFFFu, s0s, 2);
        s1s += __shfl_xor_sync(0xFFFFFFFFu, s1s, 1);
        s1s += __shfl_xor_sync(0xFFFFFFFFu, s1s, 2);
        l0 = l0 * alpha0 + s0s;
        l1 = l1 * alpha1 + s1s;
        #pragma unroll
        for (int nt = 0; nt < 4; ++nt) {
            o[nt][0] *= alpha0; o[nt][1] *= alpha0;
            o[nt][2] *= alpha1; o[nt][3] *= alpha1;
        }

        // ---- PV mma: single fp16 per (nte,kk) ----
        #pragma unroll
        for (int nte = 0; nte < 4; ++nte) {
            const u32* vhp = Vth + (8*nte + g) * ATP_;
            #pragma unroll
            for (int kk = 0; kk < 4; ++kk) {
                int cu = 8 * kk + tl;
                u32 bh0 = vhp[cu], bh1 = vhp[cu+4];
                mma_f16(o[nte][0],o[nte][1],o[nte][2],o[nte][3],
                        ph0[2*kk], ph1[2*kk], ph0[2*kk+1], ph1[2*kk+1], bh0, bh1);
            }
        }
    }

    // Epilogue
    float i0 = 1.f / l0, i1 = 1.f / l1;
    #pragma unroll
    for (int nte = 0; nte < 4; ++nte) {
        int e = 8 * nte + 2 * tl;
        float2 v0 = make_float2(o[nte][0] * i0, o[nte][1] * i0);
        float2 v1 = make_float2(o[nte][2] * i1, o[nte][3] * i1);
        *(float2*)&out[(((size_t)b * Tv_ + r0g) * Mv_ + mm) * Pv_ + h * Ev_ + e] = v0;
        *(float2*)&out[(((size_t)b * Tv_ + r1g) * Mv_ + mm) * Pv_ + h * Ev_ + e] = v1;
    }
}

// ---------------------------------------------------------------------------
extern "C" void kernel_launch(void* const* d_in, const int* in_sizes, int n_in,
                              void* d_out, int out_size)
{
    const float* inp  = (const float*)d_in[0];
    const float* pos  = (const float*)d_in[1];
    const unsigned char* mask = (const unsigned char*)d_in[2];
    const float* Wq  = (const float*)d_in[3];
    const float* Bq  = (const float*)d_in[4];
    const float* Wk  = (const float*)d_in[5];
    const float* Bk  = (const float*)d_in[6];
    const float* Wv  = (const float*)d_in[7];
    const float* Bv  = (const float*)d_in[8];
    const float* Wqt = (const float*)d_in[9];
    const float* Bqt = (const float*)d_in[10];
    const float* Wkt = (const float*)d_in[11];
    const float* Bkt = (const float*)d_in[12];
    float* out = (float*)d_out;

    const float SCALE = 0.08838834764831845f; // 1 / (2*sqrt(32))

    const int PROJ_SMEM = 4 * 64 * PJP_ * 4;              // 69632 B
    const int ATTN_SMEM = (2*128 + 64 + 32) * ATP_ * 4;   // 50688 B
    cudaFuncSetAttribute(proj_kernel, cudaFuncAttributeMaxDynamicSharedMemorySize, PROJ_SMEM);
    cudaFuncSetAttribute(attn_kernel, cudaFuncAttributeMaxDynamicSharedMemorySize, ATTN_SMEM);

    prep_kernel<<<512, 256>>>(Wq, Wk, Wv, Wqt, Wkt);

    dim3 pgrid(Mv_, BT_ / 64, 2);
    proj_kernel<<<pgrid, 128, PROJ_SMEM>>>(inp, pos, Bq, Bk, Bv, Bqt, Bkt, SCALE);

    dim3 agrid(Tv_ / 128, BMH_);
    attn_kernel<<<agrid, 256, ATTN_SMEM>>>(mask, out);
}

// round 15
// speedup vs baseline: 1.1363x; 1.0368x over previous
#include <cuda_runtime.h>
#include <cuda_bf16.h>
#include <cuda_fp16.h>
#include <math.h>

#define Bv_ 4
#define Tv_ 512
#define Mv_ 16
#define Dv_ 128
#define Pv_ 128
#define Hv_ 4
#define Ev_ 32
#define BT_ (Bv_*Tv_)      // 2048
#define BMH_ (Bv_*Mv_*Hv_) // 256

typedef unsigned int u32;
typedef unsigned short u16;

// ---------------------------------------------------------------------------
// Scratch: Q, K, V single fp16 planes; W single fp16 plane.
// ---------------------------------------------------------------------------
__device__ u16 g_Qf[BMH_ * Tv_ * 64];
__device__ u16 g_Kf[BMH_ * Tv_ * 64];
__device__ u16 g_Vf[BMH_ * Tv_ * Ev_];
__device__ u16 g_Wf[5 * Mv_ * Pv_ * Dv_];

// ---------------------------------------------------------------------------
__device__ __forceinline__ void mma_f16(float& c0, float& c1, float& c2, float& c3,
                                        u32 a0, u32 a1, u32 a2, u32 a3,
                                        u32 b0, u32 b1) {
    asm volatile("mma.sync.aligned.m16n8k16.row.col.f32.f16.f16.f32 "
                 "{%0,%1,%2,%3},{%4,%5,%6,%7},{%8,%9},{%0,%1,%2,%3};"
                 : "+f"(c0), "+f"(c1), "+f"(c2), "+f"(c3)
                 : "r"(a0), "r"(a1), "r"(a2), "r"(a3), "r"(b0), "r"(b1));
}

// fp16 hi + fp16 residual pair (for X in projection)
__device__ __forceinline__ void split2h(float x0, float x1, u32& h, u32& l) {
    __half h0 = __float2half_rn(x0), h1 = __float2half_rn(x1);
    float r0 = x0 - __half2float(h0), r1 = x1 - __half2float(h1);
    __half l0 = __float2half_rn(r0), l1 = __float2half_rn(r1);
    h = (u32)__half_as_ushort(h0) | ((u32)__half_as_ushort(h1) << 16);
    l = (u32)__half_as_ushort(l0) | ((u32)__half_as_ushort(l1) << 16);
}
// Pack two floats into f16x2 (lo = first arg).
__device__ __forceinline__ u32 cvt_f16x2(float lo, float hi) {
    u32 d; asm("cvt.rn.f16x2.f32 %0, %1, %2;" : "=r"(d) : "f"(hi), "f"(lo)); return d;
}

// ---------------------------------------------------------------------------
// Prep: convert the 5 weight tensors to a single fp16 plane.
// ---------------------------------------------------------------------------
#define NW2 (Mv_*Pv_*Dv_/2)

__global__ void prep_kernel(const float* __restrict__ Wq, const float* __restrict__ Wk,
                            const float* __restrict__ Wv, const float* __restrict__ Wqt,
                            const float* __restrict__ Wkt)
{
    int n = 5 * NW2;
    for (int i = blockIdx.x * blockDim.x + threadIdx.x; i < n; i += gridDim.x * blockDim.x) {
        int ws = i / NW2, off = i - ws * NW2;
        const float* W = (ws == 0) ? Wq : (ws == 1) ? Wk : (ws == 2) ? Wv : (ws == 3) ? Wqt : Wkt;
        float2 v = ((const float2*)W)[off];
        ((u32*)g_Wf)[i] = cvt_f16x2(v.x, v.y);
    }
}

// ---------------------------------------------------------------------------
// Projection: fp16 2-term mma (Xhi*W + Xlo*W; X split-2 exact, W single fp16).
// Block = 128 threads (4 warps). grid (m=16, ytile=32, z=2).
// z=0: q,k,v from inp[m]; z=1: q_t,k_t from pos.
// ---------------------------------------------------------------------------
#define PJP_ 68

__global__ void __launch_bounds__(128) proj_kernel(
    const float* __restrict__ inp, const float* __restrict__ pos,
    const float* __restrict__ Bq,  const float* __restrict__ Bk,
    const float* __restrict__ Bvb, const float* __restrict__ Bqt,
    const float* __restrict__ Bkt, float scaleQ)
{
    extern __shared__ u32 smp[];
    u32* Xh = smp;                    // [64][68] fp16 K-pairs
    u32* Xl = smp + 64 * PJP_;
    u32* Wf = smp + 2 * 64 * PJP_;

    int m = blockIdx.x, row0 = blockIdx.y * 64, z = blockIdx.z;
    int tid = threadIdx.x;
    int w = tid >> 5, lane = tid & 31, g = lane >> 2, tl = lane & 3;

    // Stage X tile (once): split2h from float gmem
    {
        const float* Xb = z ? pos : inp + (size_t)m * Dv_;
        int stride = z ? Dv_ : Mv_ * Dv_;
        int row = tid >> 1, k0 = (tid & 1) * 64;
        const float4* src = (const float4*)&Xb[(size_t)(row0 + row) * stride + k0];
        u32* xh = Xh + row * PJP_ + k0 / 2;
        u32* xl = Xl + row * PJP_ + k0 / 2;
        #pragma unroll
        for (int j = 0; j < 16; ++j) {
            float4 v = src[j];
            u32 h0, l0, h1, l1;
            split2h(v.x, v.y, h0, l0); split2h(v.z, v.w, h1, l1);
            xh[2*j] = h0; xh[2*j+1] = h1; xl[2*j] = l0; xl[2*j+1] = l1;
        }
    }

    int nsel = z ? 2 : 3;
    for (int si = 0; si < nsel; ++si) {
        int dsel = z ? 3 + si : si;   // 0..4 == Wq,Wk,Wv,Wqt,Wkt
        const float* Bi; float scale = 1.f;
        switch (dsel) {
            case 0:  Bi = Bq;  scale = scaleQ; break;
            case 1:  Bi = Bk;  break;
            case 2:  Bi = Bvb; break;
            case 3:  Bi = Bqt; scale = scaleQ; break;
            default: Bi = Bkt; break;
        }
        for (int ch = 0; ch < 2; ++ch) {
            __syncthreads();   // previous readers of Wf (and X stage) done
            {
                int row = tid >> 1, hf = tid & 1;
                size_t eo = (((size_t)dsel * Mv_ + m) * Pv_ + ch * 64 + row) * Dv_ + hf * 64;
                const uint4* sw = (const uint4*)(g_Wf + eo);
                uint4* dw = (uint4*)(Wf + row * PJP_ + hf * 32);
                #pragma unroll
                for (int j = 0; j < 8; ++j) dw[j] = sw[j];
            }
            __syncthreads();

            float c[8][4];
            #pragma unroll
            for (int nt = 0; nt < 8; ++nt) { c[nt][0]=c[nt][1]=c[nt][2]=c[nt][3]=0.f; }

            const u32* xh0 = Xh + (16*w + g) * PJP_;
            const u32* xh1 = Xh + (16*w + g + 8) * PJP_;
            const u32* xl0 = Xl + (16*w + g) * PJP_;
            const u32* xl1 = Xl + (16*w + g + 8) * PJP_;
            #pragma unroll
            for (int kk = 0; kk < 8; ++kk) {
                int cu = 8 * kk + tl;
                u32 ah0 = xh0[cu], ah1 = xh1[cu], ah2 = xh0[cu+4], ah3 = xh1[cu+4];
                u32 al0 = xl0[cu], al1 = xl1[cu], al2 = xl0[cu+4], al3 = xl1[cu+4];
                #pragma unroll
                for (int nt = 0; nt < 8; ++nt) {
                    const u32* wp = Wf + (8*nt + g) * PJP_;
                    u32 b0 = wp[cu], b1 = wp[cu+4];
                    mma_f16(c[nt][0],c[nt][1],c[nt][2],c[nt][3], ah0,ah1,ah2,ah3, b0,b1);
                    mma_f16(c[nt][0],c[nt][1],c[nt][2],c[nt][3], al0,al1,al2,al3, b0,b1);
                }
            }

            // Epilogue: bias, scale, fp16 pack, scatter to head layout
            u16* dst = (dsel == 2) ? g_Vf : (dsel == 1 || dsel == 4) ? g_Kf : g_Qf;
            int pitch = (dsel == 2) ? 32 : 64;
            int eoff  = (dsel >= 3) ? 32 : 0;
            int bt0 = row0 + 16*w + g;
            int bb0 = bt0 >> 9, t0 = bt0 & 511;
            int bt1 = bt0 + 8;
            int bb1 = bt1 >> 9, t1 = bt1 & 511;
            #pragma unroll
            for (int nt = 0; nt < 8; ++nt) {
                int col = ch * 64 + 8 * nt + 2 * tl;
                float b0v = Bi[m * Pv_ + col], b1v = Bi[m * Pv_ + col + 1];
                int hh = col >> 5, e = col & 31;
                float v00 = (c[nt][0] + b0v) * scale, v01 = (c[nt][1] + b1v) * scale;
                float v10 = (c[nt][2] + b0v) * scale, v11 = (c[nt][3] + b1v) * scale;
                size_t base0 = ((size_t)((bb0 * Mv_ + m) * Hv_ + hh) * Tv_ + t0) * pitch + eoff + e;
                size_t base1 = ((size_t)((bb1 * Mv_ + m) * Hv_ + hh) * Tv_ + t1) * pitch + eoff + e;
                *(u32*)&dst[base0] = cvt_f16x2(v00, v01);
                *(u32*)&dst[base1] = cvt_f16x2(v10, v11);
            }
        }
    }
}

// ---------------------------------------------------------------------------
// Flash attention: QK = single fp16 mma, PV = single fp16 mma.
// Block 256 thr (8 warps), 128-query tile x 64-key tiles, causal warp-skip
// at tile AND nt-chunk granularity.
// ---------------------------------------------------------------------------
#define ATP_ 36

__global__ void __launch_bounds__(256, 2) attn_kernel(
    const unsigned char* __restrict__ mask_raw, float* __restrict__ out)
{
    extern __shared__ u32 sma[];
    u32* Qf  = sma;                   // [128][36]
    u32* Kf  = Qf  + 128 * ATP_;      // [64][36]
    u32* Vth = Kf  +  64 * ATP_;      // [32 e][36] fp16 s-pairs

    int tid = threadIdx.x, w = tid >> 5, lane = tid & 31, g = lane >> 2, tl = lane & 3;
    int q0 = blockIdx.x * 128, bmh = blockIdx.y;
    int b = bmh >> 6, mh = bmh & 63, mm = mh >> 2, h = mh & 3;

    // Lengths inline (dtype-robust): mask[b,t,m] = t < len
    int len;
    {
        bool is_byte = (mask_raw[1] != 0);
        int p0, p1;
        if (is_byte) {
            p0 = (mask_raw[(size_t)(b * Tv_ + tid) * Mv_] != 0);
            p1 = (mask_raw[(size_t)(b * Tv_ + tid + 256) * Mv_] != 0);
        } else {
            const u32* mi = (const u32*)mask_raw;
            p0 = (mi[(size_t)(b * Tv_ + tid) * Mv_] != 0u);
            p1 = (mi[(size_t)(b * Tv_ + tid + 256) * Mv_] != 0u);
        }
        len = __syncthreads_count(p0) + __syncthreads_count(p1);
    }

    // Stage Q (single fp16 plane): 128 rows
    {
        int row = tid >> 1, hf = tid & 1;
        const uint4* sq = (const uint4*)(g_Qf + ((size_t)bmh * Tv_ + q0 + row) * 64 + hf * 32);
        uint4* dq = (uint4*)(Qf + row * ATP_ + hf * 16);
        #pragma unroll
        for (int i = 0; i < 4; ++i) dq[i] = sq[i];
    }

    float mx0 = -INFINITY, mx1 = -INFINITY, l0 = 0.f, l1 = 0.f;
    float o[4][4];
    #pragma unroll
    for (int i = 0; i < 4; ++i) { o[i][0]=o[i][1]=o[i][2]=o[i][3]=0.f; }

    int r0g = q0 + 16*w + g;
    int r1g = r0g + 8;
    int wmax = q0 + 16*w + 15;

    int smax = min(q0 + 128, len);
    for (int s0 = 0; s0 < smax; s0 += 64) {
        __syncthreads();
        // Stage K (single fp16 plane)
        {
            int row = tid >> 2, q4 = tid & 3;
            const uint4* sk = (const uint4*)(g_Kf + ((size_t)bmh * Tv_ + s0 + row) * 64 + q4 * 16);
            uint4* dk = (uint4*)(Kf + row * ATP_ + q4 * 8);
            dk[0] = sk[0]; dk[1] = sk[1];
        }
        // Stage V (fp16): warps 0..3, warp w -> e0 = 8w, lane -> s-pair
        if (w < 4) {
            int e0 = 8 * w, s2 = lane;
            const u16* ra = (const u16*)(g_Vf + ((size_t)bmh * Tv_ + s0 + 2*s2) * Ev_ + e0);
            uint4 A  = *(const uint4*)ra;
            uint4 Bx = *(const uint4*)(ra + Ev_);
            const u16* a  = (const u16*)&A;
            const u16* bb = (const u16*)&Bx;
            #pragma unroll
            for (int j = 0; j < 8; ++j)
                Vth[(e0 + j) * ATP_ + s2] = (u32)a[j] | ((u32)bb[j] << 16);
        }
        __syncthreads();

        if (s0 > wmax) continue;   // tile fully beyond this warp's causal range

        // ---- QK mma (single fp16) with nt-chunk causal skip ----
        float c[8][4];
        #pragma unroll
        for (int nt = 0; nt < 8; ++nt) { c[nt][0]=c[nt][1]=c[nt][2]=c[nt][3]=0.f; }

        const u32* qf0 = Qf + (16*w + g) * ATP_;
        const u32* qf1 = Qf + (16*w + g + 8) * ATP_;
        #pragma unroll
        for (int kk = 0; kk < 4; ++kk) {
            int cu = 8 * kk + tl;
            u32 a0 = qf0[cu], a1 = qf1[cu], a2 = qf0[cu+4], a3 = qf1[cu+4];
            #pragma unroll
            for (int nt = 0; nt < 8; ++nt) {
                if (s0 + 8 * nt <= wmax) {    // warp-uniform causal chunk skip
                    const u32* kp = Kf + (8*nt + g) * ATP_;
                    u32 b0 = kp[cu], b1 = kp[cu+4];
                    mma_f16(c[nt][0],c[nt][1],c[nt][2],c[nt][3], a0,a1,a2,a3, b0,b1);
                }
            }
        }

        // ---- softmax in registers ----
        float rm0 = -1e30f, rm1 = -1e30f;
        #pragma unroll
        for (int nt = 0; nt < 8; ++nt) {
            int sg = s0 + 8 * nt + 2 * tl;
            if (!(sg     <= r0g && sg     < len)) c[nt][0] = -1e30f;
            if (!(sg + 1 <= r0g && sg + 1 < len)) c[nt][1] = -1e30f;
            if (!(sg     <= r1g && sg     < len)) c[nt][2] = -1e30f;
            if (!(sg + 1 <= r1g && sg + 1 < len)) c[nt][3] = -1e30f;
            rm0 = fmaxf(rm0, fmaxf(c[nt][0], c[nt][1]));
            rm1 = fmaxf(rm1, fmaxf(c[nt][2], c[nt][3]));
        }
        rm0 = fmaxf(rm0, __shfl_xor_sync(0xFFFFFFFFu, rm0, 1));
        rm0 = fmaxf(rm0, __shfl_xor_sync(0xFFFFFFFFu, rm0, 2));
        rm1 = fmaxf(rm1, __shfl_xor_sync(0xFFFFFFFFu, rm1, 1));
        rm1 = fmaxf(rm1, __shfl_xor_sync(0xFFFFFFFFu, rm1, 2));

        float mn0 = fmaxf(mx0, rm0), mn1 = fmaxf(mx1, rm1);
        float alpha0 = __expf(mx0 - mn0), alpha1 = __expf(mx1 - mn1);
        mx0 = mn0; mx1 = mn1;

        u32 ph0[8], ph1[8];
        float s0s = 0.f, s1s = 0.f;
        #pragma unroll
        for (int nt = 0; nt < 8; ++nt) {
            float p00 = __expf(c[nt][0] - mn0), p01 = __expf(c[nt][1] - mn0);
            float p10 = __expf(c[nt][2] - mn1), p11 = __expf(c[nt][3] - mn1);
            s0s += p00 + p01; s1s += p10 + p11;
            ph0[nt] = cvt_f16x2(p00, p01);
            ph1[nt] = cvt_f16x2(p10, p11);
        }
        s0s += __shfl_xor_sync(0xFFFFFFFFu, s0s, 1);
        s0s += __shfl_xor_sync(0xFFFFFFFFu, s0s, 2);
        s1s += __shfl_xor_sync(0xFFFFFFFFu, s1s, 1);
        s1s += __shfl_xor_sync(0xFFFFFFFFu, s1s, 2);
        l0 = l0 * alpha0 + s0s;
        l1 = l1 * alpha1 + s1s;
        #pragma unroll
        for (int nt = 0; nt < 4; ++nt) {
            o[nt][0] *= alpha0; o[nt][1] *= alpha0;
            o[nt][2] *= alpha1; o[nt][3] *= alpha1;
        }

        // ---- PV mma: single fp16 per (nte,kk) ----
        #pragma unroll
        for (int nte = 0; nte < 4; ++nte) {
            const u32* vhp = Vth + (8*nte + g) * ATP_;
            #pragma unroll
            for (int kk = 0; kk < 4; ++kk) {
                int cu = 8 * kk + tl;
                u32 bh0 = vhp[cu], bh1 = vhp[cu+4];
                mma_f16(o[nte][0],o[nte][1],o[nte][2],o[nte][3],
                        ph0[2*kk], ph1[2*kk], ph0[2*kk+1], ph1[2*kk+1], bh0, bh1);
            }
        }
    }

    // Epilogue
    float i0 = 1.f / l0, i1 = 1.f / l1;
    #pragma unroll
    for (int nte = 0; nte < 4; ++nte) {
        int e = 8 * nte + 2 * tl;
        float2 v0 = make_float2(o[nte][0] * i0, o[nte][1] * i0);
        float2 v1 = make_float2(o[nte][2] * i1, o[nte][3] * i1);
        *(float2*)&out[(((size_t)b * Tv_ + r0g) * Mv_ + mm) * Pv_ + h * Ev_ + e] = v0;
        *(float2*)&out[(((size_t)b * Tv_ + r1g) * Mv_ + mm) * Pv_ + h * Ev_ + e] = v1;
    }
}

// ---------------------------------------------------------------------------
extern "C" void kernel_launch(void* const* d_in, const int* in_sizes, int n_in,
                              void* d_out, int out_size)
{
    const float* inp  = (const float*)d_in[0];
    const float* pos  = (const float*)d_in[1];
    const unsigned char* mask = (const unsigned char*)d_in[2];
    const float* Wq  = (const float*)d_in[3];
    const float* Bq  = (const float*)d_in[4];
    const float* Wk  = (const float*)d_in[5];
    const float* Bk  = (const float*)d_in[6];
    const float* Wv  = (const float*)d_in[7];
    const float* Bv  = (const float*)d_in[8];
    const float* Wqt = (const float*)d_in[9];
    const float* Bqt = (const float*)d_in[10];
    const float* Wkt = (const float*)d_in[11];
    const float* Bkt = (const float*)d_in[12];
    float* out = (float*)d_out;

    const float SCALE = 0.08838834764831845f; // 1 / (2*sqrt(32))

    const int PROJ_SMEM = 3 * 64 * PJP_ * 4;              // 52224 B
    const int ATTN_SMEM = (128 + 64 + 32) * ATP_ * 4;     // 32256 B
    cudaFuncSetAttribute(proj_kernel, cudaFuncAttributeMaxDynamicSharedMemorySize, PROJ_SMEM);
    cudaFuncSetAttribute(attn_kernel, cudaFuncAttributeMaxDynamicSharedMemorySize, ATTN_SMEM);

    prep_kernel<<<512, 256>>>(Wq, Wk, Wv, Wqt, Wkt);

    dim3 pgrid(Mv_, BT_ / 64, 2);
    proj_kernel<<<pgrid, 128, PROJ_SMEM>>>(inp, pos, Bq, Bk, Bv, Bqt, Bkt, SCALE);

    dim3 agrid(Tv_ / 128, BMH_);
    attn_kernel<<<agrid, 256, ATTN_SMEM>>>(mask, out);
}

// round 16
// speedup vs baseline: 1.5429x; 1.3578x over previous
#include <cuda_runtime.h>
#include <cuda_bf16.h>
#include <cuda_fp16.h>
#include <math.h>

#define Bv_ 4
#define Tv_ 512
#define Mv_ 16
#define Dv_ 128
#define Pv_ 128
#define Hv_ 4
#define Ev_ 32
#define BT_ (Bv_*Tv_)      // 2048
#define BMH_ (Bv_*Mv_*Hv_) // 256

typedef unsigned int u32;
typedef unsigned short u16;

// ---------------------------------------------------------------------------
// Scratch: Q, K, V single fp16 planes.
// ---------------------------------------------------------------------------
__device__ u16 g_Qf[BMH_ * Tv_ * 64];
__device__ u16 g_Kf[BMH_ * Tv_ * 64];
__device__ u16 g_Vf[BMH_ * Tv_ * Ev_];

// ---------------------------------------------------------------------------
__device__ __forceinline__ void mma_f16(float& c0, float& c1, float& c2, float& c3,
                                        u32 a0, u32 a1, u32 a2, u32 a3,
                                        u32 b0, u32 b1) {
    asm volatile("mma.sync.aligned.m16n8k16.row.col.f32.f16.f16.f32 "
                 "{%0,%1,%2,%3},{%4,%5,%6,%7},{%8,%9},{%0,%1,%2,%3};"
                 : "+f"(c0), "+f"(c1), "+f"(c2), "+f"(c3)
                 : "r"(a0), "r"(a1), "r"(a2), "r"(a3), "r"(b0), "r"(b1));
}

// fp16 hi + fp16 residual pair (for X in projection)
__device__ __forceinline__ void split2h(float x0, float x1, u32& h, u32& l) {
    __half h0 = __float2half_rn(x0), h1 = __float2half_rn(x1);
    float r0 = x0 - __half2float(h0), r1 = x1 - __half2float(h1);
    __half l0 = __float2half_rn(r0), l1 = __float2half_rn(r1);
    h = (u32)__half_as_ushort(h0) | ((u32)__half_as_ushort(h1) << 16);
    l = (u32)__half_as_ushort(l0) | ((u32)__half_as_ushort(l1) << 16);
}
// Pack two floats into f16x2 (lo = first arg).
__device__ __forceinline__ u32 cvt_f16x2(float lo, float hi) {
    u32 d; asm("cvt.rn.f16x2.f32 %0, %1, %2;" : "=r"(d) : "f"(hi), "f"(lo)); return d;
}

// ---------------------------------------------------------------------------
// Projection: fp16 2-term mma (Xhi*W + Xlo*W; X split-2 exact, W single fp16
// converted inline from float gmem). Block = 128 threads (4 warps).
// grid (m=16, ytile=32, z=2). z=0: q,k,v from inp[m]; z=1: q_t,k_t from pos.
// Double-buffered W smem, W for phase p+1 prefetched during phase p compute,
// ONE sync per phase.
// ---------------------------------------------------------------------------
#define PJP_ 68

__global__ void __launch_bounds__(128) proj_kernel(
    const float* __restrict__ inp, const float* __restrict__ pos,
    const float* __restrict__ Wq,  const float* __restrict__ Bq,
    const float* __restrict__ Wk,  const float* __restrict__ Bk,
    const float* __restrict__ Wv,  const float* __restrict__ Bvb,
    const float* __restrict__ Wqt, const float* __restrict__ Bqt,
    const float* __restrict__ Wkt, const float* __restrict__ Bkt,
    float scaleQ)
{
    extern __shared__ u32 smp[];
    u32* Xh = smp;                        // [64][68] fp16 K-pairs
    u32* Xl = smp + 64 * PJP_;
    u32* Wb0 = smp + 2 * 64 * PJP_;       // double-buffered W
    u32* Wb1 = smp + 3 * 64 * PJP_;

    int m = blockIdx.x, row0 = blockIdx.y * 64, z = blockIdx.z;
    int tid = threadIdx.x;
    int w = tid >> 5, lane = tid & 31, g = lane >> 2, tl = lane & 3;

    // Stage X tile (once): split2h from float gmem (published by phase-0 sync)
    {
        const float* Xb = z ? pos : inp + (size_t)m * Dv_;
        int stride = z ? Dv_ : Mv_ * Dv_;
        int row = tid >> 1, k0 = (tid & 1) * 64;
        const float4* src = (const float4*)&Xb[(size_t)(row0 + row) * stride + k0];
        u32* xh = Xh + row * PJP_ + k0 / 2;
        u32* xl = Xl + row * PJP_ + k0 / 2;
        #pragma unroll
        for (int j = 0; j < 16; ++j) {
            float4 v = src[j];
            u32 h0, l0, h1, l1;
            split2h(v.x, v.y, h0, l0); split2h(v.z, v.w, h1, l1);
            xh[2*j] = h0; xh[2*j+1] = h1; xl[2*j] = l0; xl[2*j+1] = l1;
        }
    }

    int nph = z ? 4 : 6;   // phases = (si, ch); dsel = z ? 3+si : si
    int srow = tid >> 1, shf = tid & 1;

    uint4 wreg[8];
    // load + convert W for phase p into wreg
    auto loadW = [&](int p) {
        int si = p >> 1, ch = p & 1;
        int dsel = z ? 3 + si : si;
        const float* W = (dsel == 0) ? Wq : (dsel == 1) ? Wk : (dsel == 2) ? Wv
                        : (dsel == 3) ? Wqt : Wkt;
        const float4* src = (const float4*)&W[(((size_t)m * Pv_) + ch * 64 + srow) * Dv_ + shf * 64];
        #pragma unroll
        for (int j = 0; j < 8; ++j) {
            float4 a = src[2*j], bq = src[2*j+1];
            wreg[j] = make_uint4(cvt_f16x2(a.x, a.y), cvt_f16x2(a.z, a.w),
                                 cvt_f16x2(bq.x, bq.y), cvt_f16x2(bq.z, bq.w));
        }
    };

    loadW(0);
    for (int p = 0; p < nph; ++p) {
        u32* Wf = (p & 1) ? Wb1 : Wb0;
        // STS current W regs (prev readers of this buffer done before sync p-1)
        {
            uint4* dw = (uint4*)(Wf + srow * PJP_ + shf * 32);
            #pragma unroll
            for (int j = 0; j < 8; ++j) dw[j] = wreg[j];
        }
        if (p + 1 < nph) loadW(p + 1);   // prefetch next phase (latency hidden by compute)
        __syncthreads();

        int si = p >> 1, ch = p & 1;
        int dsel = z ? 3 + si : si;
        const float* Bi; float scale = 1.f;
        switch (dsel) {
            case 0:  Bi = Bq;  scale = scaleQ; break;
            case 1:  Bi = Bk;  break;
            case 2:  Bi = Bvb; break;
            case 3:  Bi = Bqt; scale = scaleQ; break;
            default: Bi = Bkt; break;
        }

        float c[8][4];
        #pragma unroll
        for (int nt = 0; nt < 8; ++nt) { c[nt][0]=c[nt][1]=c[nt][2]=c[nt][3]=0.f; }

        const u32* xh0 = Xh + (16*w + g) * PJP_;
        const u32* xh1 = Xh + (16*w + g + 8) * PJP_;
        const u32* xl0 = Xl + (16*w + g) * PJP_;
        const u32* xl1 = Xl + (16*w + g + 8) * PJP_;
        #pragma unroll
        for (int kk = 0; kk < 8; ++kk) {
            int cu = 8 * kk + tl;
            u32 ah0 = xh0[cu], ah1 = xh1[cu], ah2 = xh0[cu+4], ah3 = xh1[cu+4];
            u32 al0 = xl0[cu], al1 = xl1[cu], al2 = xl0[cu+4], al3 = xl1[cu+4];
            #pragma unroll
            for (int nt = 0; nt < 8; ++nt) {
                const u32* wp = Wf + (8*nt + g) * PJP_;
                u32 b0 = wp[cu], b1 = wp[cu+4];
                mma_f16(c[nt][0],c[nt][1],c[nt][2],c[nt][3], ah0,ah1,ah2,ah3, b0,b1);
                mma_f16(c[nt][0],c[nt][1],c[nt][2],c[nt][3], al0,al1,al2,al3, b0,b1);
            }
        }

        // Epilogue: bias, scale, fp16 pack, scatter to head layout
        u16* dst = (dsel == 2) ? g_Vf : (dsel == 1 || dsel == 4) ? g_Kf : g_Qf;
        int pitch = (dsel == 2) ? 32 : 64;
        int eoff  = (dsel >= 3) ? 32 : 0;
        int bt0 = row0 + 16*w + g;
        int bb0 = bt0 >> 9, t0 = bt0 & 511;
        int bt1 = bt0 + 8;
        int bb1 = bt1 >> 9, t1 = bt1 & 511;
        #pragma unroll
        for (int nt = 0; nt < 8; ++nt) {
            int col = ch * 64 + 8 * nt + 2 * tl;
            float b0v = Bi[m * Pv_ + col], b1v = Bi[m * Pv_ + col + 1];
            int hh = col >> 5, e = col & 31;
            float v00 = (c[nt][0] + b0v) * scale, v01 = (c[nt][1] + b1v) * scale;
            float v10 = (c[nt][2] + b0v) * scale, v11 = (c[nt][3] + b1v) * scale;
            size_t base0 = ((size_t)((bb0 * Mv_ + m) * Hv_ + hh) * Tv_ + t0) * pitch + eoff + e;
            size_t base1 = ((size_t)((bb1 * Mv_ + m) * Hv_ + hh) * Tv_ + t1) * pitch + eoff + e;
            *(u32*)&dst[base0] = cvt_f16x2(v00, v01);
            *(u32*)&dst[base1] = cvt_f16x2(v10, v11);
        }
    }
}

// ---------------------------------------------------------------------------
// Flash attention: QK & PV single fp16 mma. Block 256 thr (8 warps),
// 128-query tile x 64-key tiles. Double-buffered K/V smem, next tile
// prefetched into regs during compute, ONE sync per tile. Causal skip at
// tile and nt-chunk granularity.
// ---------------------------------------------------------------------------
#define ATP_ 36

__global__ void __launch_bounds__(256, 2) attn_kernel(
    const unsigned char* __restrict__ mask_raw, float* __restrict__ out)
{
    extern __shared__ u32 sma[];
    u32* Qf  = sma;                       // [128][36]
    u32* Kb0 = Qf  + 128 * ATP_;          // [64][36] x2
    u32* Kb1 = Kb0 +  64 * ATP_;
    u32* Vb0 = Kb1 +  64 * ATP_;          // [32][36] x2 (fp16 s-pairs)
    u32* Vb1 = Vb0 +  32 * ATP_;

    int tid = threadIdx.x, w = tid >> 5, lane = tid & 31, g = lane >> 2, tl = lane & 3;
    int q0 = blockIdx.x * 128, bmh = blockIdx.y;
    int b = bmh >> 6, mh = bmh & 63, mm = mh >> 2, h = mh & 3;

    // Lengths inline (dtype-robust): mask[b,t,m] = t < len
    int len;
    {
        bool is_byte = (mask_raw[1] != 0);
        int p0, p1;
        if (is_byte) {
            p0 = (mask_raw[(size_t)(b * Tv_ + tid) * Mv_] != 0);
            p1 = (mask_raw[(size_t)(b * Tv_ + tid + 256) * Mv_] != 0);
        } else {
            const u32* mi = (const u32*)mask_raw;
            p0 = (mi[(size_t)(b * Tv_ + tid) * Mv_] != 0u);
            p1 = (mi[(size_t)(b * Tv_ + tid + 256) * Mv_] != 0u);
        }
        len = __syncthreads_count(p0) + __syncthreads_count(p1);
    }

    // Stage Q (published by tile-0 sync)
    {
        int row = tid >> 1, hf = tid & 1;
        const uint4* sq = (const uint4*)(g_Qf + ((size_t)bmh * Tv_ + q0 + row) * 64 + hf * 32);
        uint4* dq = (uint4*)(Qf + row * ATP_ + hf * 16);
        #pragma unroll
        for (int i = 0; i < 4; ++i) dq[i] = sq[i];
    }

    float mx0 = -INFINITY, mx1 = -INFINITY, l0 = 0.f, l1 = 0.f;
    float o[4][4];
    #pragma unroll
    for (int i = 0; i < 4; ++i) { o[i][0]=o[i][1]=o[i][2]=o[i][3]=0.f; }

    int r0g = q0 + 16*w + g;
    int r1g = r0g + 8;
    int wmax = q0 + 16*w + 15;

    int smax = min(q0 + 128, len);
    int ntile = (smax + 63) >> 6;

    int krow = tid >> 2, kq4 = tid & 3;   // K staging coords
    int ve0 = 8 * w, vs2 = lane;          // V staging coords (warps 0..3)

    uint4 kreg0, kreg1, vreg0, vreg1;
    auto preload = [&](int s0) {
        const uint4* sk = (const uint4*)(g_Kf + ((size_t)bmh * Tv_ + s0 + krow) * 64 + kq4 * 16);
        kreg0 = sk[0]; kreg1 = sk[1];
        if (w < 4) {
            const u16* ra = (const u16*)(g_Vf + ((size_t)bmh * Tv_ + s0 + 2*vs2) * Ev_ + ve0);
            vreg0 = *(const uint4*)ra;
            vreg1 = *(const uint4*)(ra + Ev_);
        }
    };

    preload(0);
    for (int it = 0; it < ntile; ++it) {
        int s0 = it << 6;
        u32* Kf  = (it & 1) ? Kb1 : Kb0;
        u32* Vth = (it & 1) ? Vb1 : Vb0;
        // STS staged regs (prev readers of this buffer finished before sync it-1)
        {
            uint4* dk = (uint4*)(Kf + krow * ATP_ + kq4 * 8);
            dk[0] = kreg0; dk[1] = kreg1;
            if (w < 4) {
                const u16* a  = (const u16*)&vreg0;
                const u16* bb = (const u16*)&vreg1;
                #pragma unroll
                for (int j = 0; j < 8; ++j)
                    Vth[(ve0 + j) * ATP_ + vs2] = (u32)a[j] | ((u32)bb[j] << 16);
            }
        }
        if (it + 1 < ntile) preload((it + 1) << 6);   // hide LDG behind compute
        __syncthreads();

        if (s0 > wmax) continue;   // tile fully beyond this warp's causal range

        // ---- QK mma (single fp16) with nt-chunk causal skip ----
        float c[8][4];
        #pragma unroll
        for (int nt = 0; nt < 8; ++nt) { c[nt][0]=c[nt][1]=c[nt][2]=c[nt][3]=0.f; }

        const u32* qf0 = Qf + (16*w + g) * ATP_;
        const u32* qf1 = Qf + (16*w + g + 8) * ATP_;
        #pragma unroll
        for (int kk = 0; kk < 4; ++kk) {
            int cu = 8 * kk + tl;
            u32 a0 = qf0[cu], a1 = qf1[cu], a2 = qf0[cu+4], a3 = qf1[cu+4];
            #pragma unroll
            for (int nt = 0; nt < 8; ++nt) {
                if (s0 + 8 * nt <= wmax) {    // warp-uniform causal chunk skip
                    const u32* kp = Kf + (8*nt + g) * ATP_;
                    u32 b0 = kp[cu], b1 = kp[cu+4];
                    mma_f16(c[nt][0],c[nt][1],c[nt][2],c[nt][3], a0,a1,a2,a3, b0,b1);
                }
            }
        }

        // ---- softmax in registers ----
        float rm0 = -1e30f, rm1 = -1e30f;
        #pragma unroll
        for (int nt = 0; nt < 8; ++nt) {
            int sg = s0 + 8 * nt + 2 * tl;
            if (!(sg     <= r0g && sg     < len)) c[nt][0] = -1e30f;
            if (!(sg + 1 <= r0g && sg + 1 < len)) c[nt][1] = -1e30f;
            if (!(sg     <= r1g && sg     < len)) c[nt][2] = -1e30f;
            if (!(sg + 1 <= r1g && sg + 1 < len)) c[nt][3] = -1e30f;
            rm0 = fmaxf(rm0, fmaxf(c[nt][0], c[nt][1]));
            rm1 = fmaxf(rm1, fmaxf(c[nt][2], c[nt][3]));
        }
        rm0 = fmaxf(rm0, __shfl_xor_sync(0xFFFFFFFFu, rm0, 1));
        rm0 = fmaxf(rm0, __shfl_xor_sync(0xFFFFFFFFu, rm0, 2));
        rm1 = fmaxf(rm1, __shfl_xor_sync(0xFFFFFFFFu, rm1, 1));
        rm1 = fmaxf(rm1, __shfl_xor_sync(0xFFFFFFFFu, rm1, 2));

        float mn0 = fmaxf(mx0, rm0), mn1 = fmaxf(mx1, rm1);
        float alpha0 = __expf(mx0 - mn0), alpha1 = __expf(mx1 - mn1);
        mx0 = mn0; mx1 = mn1;

        u32 ph0[8], ph1[8];
        float s0s = 0.f, s1s = 0.f;
        #pragma unroll
        for (int nt = 0; nt < 8; ++nt) {
            float p00 = __expf(c[nt][0] - mn0), p01 = __expf(c[nt][1] - mn0);
            float p10 = __expf(c[nt][2] - mn1), p11 = __expf(c[nt][3] - mn1);
            s0s += p00 + p01; s1s += p10 + p11;
            ph0[nt] = cvt_f16x2(p00, p01);
            ph1[nt] = cvt_f16x2(p10, p11);
        }
        s0s += __shfl_xor_sync(0xFFFFFFFFu, s0s, 1);
        s0s += __shfl_xor_sync(0xFFFFFFFFu, s0s, 2);
        s1s += __shfl_xor_sync(0xFFFFFFFFu, s1s, 1);
        s1s += __shfl_xor_sync(0xFFFFFFFFu, s1s, 2);
        l0 = l0 * alpha0 + s0s;
        l1 = l1 * alpha1 + s1s;
        #pragma unroll
        for (int nt = 0; nt < 4; ++nt) {
            o[nt][0] *= alpha0; o[nt][1] *= alpha0;
            o[nt][2] *= alpha1; o[nt][3] *= alpha1;
        }

        // ---- PV mma: single fp16 per (nte,kk) ----
        #pragma unroll
        for (int nte = 0; nte < 4; ++nte) {
            const u32* vhp = Vth + (8*nte + g) * ATP_;
            #pragma unroll
            for (int kk = 0; kk < 4; ++kk) {
                int cu = 8 * kk + tl;
                u32 bh0 = vhp[cu], bh1 = vhp[cu+4];
                mma_f16(o[nte][0],o[nte][1],o[nte][2],o[nte][3],
                        ph0[2*kk], ph1[2*kk], ph0[2*kk+1], ph1[2*kk+1], bh0, bh1);
            }
        }
    }

    // Epilogue
    float i0 = 1.f / l0, i1 = 1.f / l1;
    #pragma unroll
    for (int nte = 0; nte < 4; ++nte) {
        int e = 8 * nte + 2 * tl;
        float2 v0 = make_float2(o[nte][0] * i0, o[nte][1] * i0);
        float2 v1 = make_float2(o[nte][2] * i1, o[nte][3] * i1);
        *(float2*)&out[(((size_t)b * Tv_ + r0g) * Mv_ + mm) * Pv_ + h * Ev_ + e] = v0;
        *(float2*)&out[(((size_t)b * Tv_ + r1g) * Mv_ + mm) * Pv_ + h * Ev_ + e] = v1;
    }
}

// ---------------------------------------------------------------------------
extern "C" void kernel_launch(void* const* d_in, const int* in_sizes, int n_in,
                              void* d_out, int out_size)
{
    const float* inp  = (const float*)d_in[0];
    const float* pos  = (const float*)d_in[1];
    const unsigned char* mask = (const unsigned char*)d_in[2];
    const float* Wq  = (const float*)d_in[3];
    const float* Bq  = (const float*)d_in[4];
    const float* Wk  = (const float*)d_in[5];
    const float* Bk  = (const float*)d_in[6];
    const float* Wv  = (const float*)d_in[7];
    const float* Bv  = (const float*)d_in[8];
    const float* Wqt = (const float*)d_in[9];
    const float* Bqt = (const float*)d_in[10];
    const float* Wkt = (const float*)d_in[11];
    const float* Bkt = (const float*)d_in[12];
    float* out = (float*)d_out;

    const float SCALE = 0.08838834764831845f; // 1 / (2*sqrt(32))

    const int PROJ_SMEM = 4 * 64 * PJP_ * 4;                    // 69632 B
    const int ATTN_SMEM = (128 + 2*64 + 2*32) * ATP_ * 4;       // 46080 B
    cudaFuncSetAttribute(proj_kernel, cudaFuncAttributeMaxDynamicSharedMemorySize, PROJ_SMEM);
    cudaFuncSetAttribute(attn_kernel, cudaFuncAttributeMaxDynamicSharedMemorySize, ATTN_SMEM);

    dim3 pgrid(Mv_, BT_ / 64, 2);
    proj_kernel<<<pgrid, 128, PROJ_SMEM>>>(inp, pos,
        Wq, Bq, Wk, Bk, Wv, Bv, Wqt, Bqt, Wkt, Bkt, SCALE);

    dim3 agrid(Tv_ / 128, BMH_);
    attn_kernel<<<agrid, 256, ATTN_SMEM>>>(mask, out);
}

// round 17
// speedup vs baseline: 1.8259x; 1.1834x over previous
#include <cuda_runtime.h>
#include <cuda_bf16.h>
#include <cuda_fp16.h>
#include <math.h>

#define Bv_ 4
#define Tv_ 512
#define Mv_ 16
#define Dv_ 128
#define Pv_ 128
#define Hv_ 4
#define Ev_ 32
#define BT_ (Bv_*Tv_)      // 2048
#define BMH_ (Bv_*Mv_*Hv_) // 256

typedef unsigned int u32;
typedef unsigned short u16;

// ---------------------------------------------------------------------------
// Scratch: Q, K, V single fp16 planes.
// ---------------------------------------------------------------------------
__device__ u16 g_Qf[BMH_ * Tv_ * 64];
__device__ u16 g_Kf[BMH_ * Tv_ * 64];
__device__ u16 g_Vf[BMH_ * Tv_ * Ev_];

// ---------------------------------------------------------------------------
__device__ __forceinline__ void mma_f16(float& c0, float& c1, float& c2, float& c3,
                                        u32 a0, u32 a1, u32 a2, u32 a3,
                                        u32 b0, u32 b1) {
    asm volatile("mma.sync.aligned.m16n8k16.row.col.f32.f16.f16.f32 "
                 "{%0,%1,%2,%3},{%4,%5,%6,%7},{%8,%9},{%0,%1,%2,%3};"
                 : "+f"(c0), "+f"(c1), "+f"(c2), "+f"(c3)
                 : "r"(a0), "r"(a1), "r"(a2), "r"(a3), "r"(b0), "r"(b1));
}

// Pack two floats into f16x2 (lo = first arg).
__device__ __forceinline__ u32 cvt_f16x2(float lo, float hi) {
    u32 d; asm("cvt.rn.f16x2.f32 %0, %1, %2;" : "=r"(d) : "f"(hi), "f"(lo)); return d;
}

// ---------------------------------------------------------------------------
// Projection: single fp16 mma (X fp16 * W fp16, both converted inline from
// float gmem). Block = 256 threads (8 warps), 128-row x 64-col phases.
// grid (m=16, ytile=16, z=2). z=0: q,k,v from inp[m]; z=1: q_t,k_t from pos.
// Double-buffered W smem, W for phase p+1 prefetched during phase p compute,
// ONE sync per phase. Warp w owns rows 16w..16w+15.
// ---------------------------------------------------------------------------
#define PJP_ 68

__global__ void __launch_bounds__(256) proj_kernel(
    const float* __restrict__ inp, const float* __restrict__ pos,
    const float* __restrict__ Wq,  const float* __restrict__ Bq,
    const float* __restrict__ Wk,  const float* __restrict__ Bk,
    const float* __restrict__ Wv,  const float* __restrict__ Bvb,
    const float* __restrict__ Wqt, const float* __restrict__ Bqt,
    const float* __restrict__ Wkt, const float* __restrict__ Bkt,
    float scaleQ)
{
    extern __shared__ u32 smp[];
    u32* Xf  = smp;                        // [128][68] fp16 K-pairs
    u32* Wb0 = smp + 128 * PJP_;           // double-buffered W [64][68]
    u32* Wb1 = Wb0 + 64 * PJP_;

    int m = blockIdx.x, row0 = blockIdx.y * 128, z = blockIdx.z;
    int tid = threadIdx.x;
    int w = tid >> 5, lane = tid & 31, g = lane >> 2, tl = lane & 3;

    // Stage X tile (once): cvt from float gmem (published by phase-0 sync)
    {
        const float* Xb = z ? pos : inp + (size_t)m * Dv_;
        int stride = z ? Dv_ : Mv_ * Dv_;
        int row = tid >> 1, k0 = (tid & 1) * 64;
        const float4* src = (const float4*)&Xb[(size_t)(row0 + row) * stride + k0];
        u32* xf = Xf + row * PJP_ + k0 / 2;
        #pragma unroll
        for (int j = 0; j < 16; ++j) {
            float4 v = src[j];
            xf[2*j]   = cvt_f16x2(v.x, v.y);
            xf[2*j+1] = cvt_f16x2(v.z, v.w);
        }
    }

    int nph = z ? 4 : 6;   // phases = (si, ch); dsel = z ? 3+si : si
    int wrow = tid >> 2, wq4 = tid & 3;    // W staging coords (64 rows x 4 quarters)

    uint4 wreg[4];
    auto loadW = [&](int p) {
        int si = p >> 1, ch = p & 1;
        int dsel = z ? 3 + si : si;
        const float* W = (dsel == 0) ? Wq : (dsel == 1) ? Wk : (dsel == 2) ? Wv
                        : (dsel == 3) ? Wqt : Wkt;
        const float4* src = (const float4*)&W[(((size_t)m * Pv_) + ch * 64 + wrow) * Dv_ + wq4 * 32];
        #pragma unroll
        for (int j = 0; j < 4; ++j) {
            float4 a = src[2*j], bq = src[2*j+1];
            wreg[j] = make_uint4(cvt_f16x2(a.x, a.y), cvt_f16x2(a.z, a.w),
                                 cvt_f16x2(bq.x, bq.y), cvt_f16x2(bq.z, bq.w));
        }
    };

    loadW(0);
    for (int p = 0; p < nph; ++p) {
        u32* Wf = (p & 1) ? Wb1 : Wb0;
        // STS current W regs (prev readers of this buffer done before sync p-1)
        {
            uint4* dw = (uint4*)(Wf + wrow * PJP_ + wq4 * 16);
            #pragma unroll
            for (int j = 0; j < 4; ++j) dw[j] = wreg[j];
        }
        if (p + 1 < nph) loadW(p + 1);   // prefetch next phase (hidden by compute)
        __syncthreads();

        int si = p >> 1, ch = p & 1;
        int dsel = z ? 3 + si : si;
        const float* Bi; float scale = 1.f;
        switch (dsel) {
            case 0:  Bi = Bq;  scale = scaleQ; break;
            case 1:  Bi = Bk;  break;
            case 2:  Bi = Bvb; break;
            case 3:  Bi = Bqt; scale = scaleQ; break;
            default: Bi = Bkt; break;
        }

        float c[8][4];
        #pragma unroll
        for (int nt = 0; nt < 8; ++nt) { c[nt][0]=c[nt][1]=c[nt][2]=c[nt][3]=0.f; }

        const u32* xf0 = Xf + (16*w + g) * PJP_;
        const u32* xf1 = Xf + (16*w + g + 8) * PJP_;
        #pragma unroll
        for (int kk = 0; kk < 8; ++kk) {
            int cu = 8 * kk + tl;
            u32 a0 = xf0[cu], a1 = xf1[cu], a2 = xf0[cu+4], a3 = xf1[cu+4];
            #pragma unroll
            for (int nt = 0; nt < 8; ++nt) {
                const u32* wp = Wf + (8*nt + g) * PJP_;
                u32 b0 = wp[cu], b1 = wp[cu+4];
                mma_f16(c[nt][0],c[nt][1],c[nt][2],c[nt][3], a0,a1,a2,a3, b0,b1);
            }
        }

        // Epilogue: bias, scale, fp16 pack, scatter to head layout
        u16* dst = (dsel == 2) ? g_Vf : (dsel == 1 || dsel == 4) ? g_Kf : g_Qf;
        int pitch = (dsel == 2) ? 32 : 64;
        int eoff  = (dsel >= 3) ? 32 : 0;
        int bt0 = row0 + 16*w + g;
        int bb0 = bt0 >> 9, t0 = bt0 & 511;
        int bt1 = bt0 + 8;
        int bb1 = bt1 >> 9, t1 = bt1 & 511;
        #pragma unroll
        for (int nt = 0; nt < 8; ++nt) {
            int col = ch * 64 + 8 * nt + 2 * tl;
            float b0v = Bi[m * Pv_ + col], b1v = Bi[m * Pv_ + col + 1];
            int hh = col >> 5, e = col & 31;
            float v00 = (c[nt][0] + b0v) * scale, v01 = (c[nt][1] + b1v) * scale;
            float v10 = (c[nt][2] + b0v) * scale, v11 = (c[nt][3] + b1v) * scale;
            size_t base0 = ((size_t)((bb0 * Mv_ + m) * Hv_ + hh) * Tv_ + t0) * pitch + eoff + e;
            size_t base1 = ((size_t)((bb1 * Mv_ + m) * Hv_ + hh) * Tv_ + t1) * pitch + eoff + e;
            *(u32*)&dst[base0] = cvt_f16x2(v00, v01);
            *(u32*)&dst[base1] = cvt_f16x2(v10, v11);
        }
    }
}

// ---------------------------------------------------------------------------
// Flash attention: QK & PV single fp16 mma. Block 256 thr (8 warps),
// 128-query tile x 64-key tiles. Double-buffered K/V smem, next tile
// prefetched into regs during compute, ONE sync per tile. Causal skip at
// tile and nt-chunk granularity. (Unchanged from R16.)
// ---------------------------------------------------------------------------
#define ATP_ 36

__global__ void __launch_bounds__(256, 2) attn_kernel(
    const unsigned char* __restrict__ mask_raw, float* __restrict__ out)
{
    extern __shared__ u32 sma[];
    u32* Qf  = sma;                       // [128][36]
    u32* Kb0 = Qf  + 128 * ATP_;          // [64][36] x2
    u32* Kb1 = Kb0 +  64 * ATP_;
    u32* Vb0 = Kb1 +  64 * ATP_;          // [32][36] x2 (fp16 s-pairs)
    u32* Vb1 = Vb0 +  32 * ATP_;

    int tid = threadIdx.x, w = tid >> 5, lane = tid & 31, g = lane >> 2, tl = lane & 3;
    int q0 = blockIdx.x * 128, bmh = blockIdx.y;
    int b = bmh >> 6, mh = bmh & 63, mm = mh >> 2, h = mh & 3;

    // Lengths inline (dtype-robust): mask[b,t,m] = t < len
    int len;
    {
        bool is_byte = (mask_raw[1] != 0);
        int p0, p1;
        if (is_byte) {
            p0 = (mask_raw[(size_t)(b * Tv_ + tid) * Mv_] != 0);
            p1 = (mask_raw[(size_t)(b * Tv_ + tid + 256) * Mv_] != 0);
        } else {
            const u32* mi = (const u32*)mask_raw;
            p0 = (mi[(size_t)(b * Tv_ + tid) * Mv_] != 0u);
            p1 = (mi[(size_t)(b * Tv_ + tid + 256) * Mv_] != 0u);
        }
        len = __syncthreads_count(p0) + __syncthreads_count(p1);
    }

    // Stage Q (published by tile-0 sync)
    {
        int row = tid >> 1, hf = tid & 1;
        const uint4* sq = (const uint4*)(g_Qf + ((size_t)bmh * Tv_ + q0 + row) * 64 + hf * 32);
        uint4* dq = (uint4*)(Qf + row * ATP_ + hf * 16);
        #pragma unroll
        for (int i = 0; i < 4; ++i) dq[i] = sq[i];
    }

    float mx0 = -INFINITY, mx1 = -INFINITY, l0 = 0.f, l1 = 0.f;
    float o[4][4];
    #pragma unroll
    for (int i = 0; i < 4; ++i) { o[i][0]=o[i][1]=o[i][2]=o[i][3]=0.f; }

    int r0g = q0 + 16*w + g;
    int r1g = r0g + 8;
    int wmax = q0 + 16*w + 15;

    int smax = min(q0 + 128, len);
    int ntile = (smax + 63) >> 6;

    int krow = tid >> 2, kq4 = tid & 3;   // K staging coords
    int ve0 = 8 * w, vs2 = lane;          // V staging coords (warps 0..3)

    uint4 kreg0, kreg1, vreg0, vreg1;
    auto preload = [&](int s0) {
        const uint4* sk = (const uint4*)(g_Kf + ((size_t)bmh * Tv_ + s0 + krow) * 64 + kq4 * 16);
        kreg0 = sk[0]; kreg1 = sk[1];
        if (w < 4) {
            const u16* ra = (const u16*)(g_Vf + ((size_t)bmh * Tv_ + s0 + 2*vs2) * Ev_ + ve0);
            vreg0 = *(const uint4*)ra;
            vreg1 = *(const uint4*)(ra + Ev_);
        }
    };

    preload(0);
    for (int it = 0; it < ntile; ++it) {
        int s0 = it << 6;
        u32* Kf  = (it & 1) ? Kb1 : Kb0;
        u32* Vth = (it & 1) ? Vb1 : Vb0;
        // STS staged regs (prev readers of this buffer finished before sync it-1)
        {
            uint4* dk = (uint4*)(Kf + krow * ATP_ + kq4 * 8);
            dk[0] = kreg0; dk[1] = kreg1;
            if (w < 4) {
                const u16* a  = (const u16*)&vreg0;
                const u16* bb = (const u16*)&vreg1;
                #pragma unroll
                for (int j = 0; j < 8; ++j)
                    Vth[(ve0 + j) * ATP_ + vs2] = (u32)a[j] | ((u32)bb[j] << 16);
            }
        }
        if (it + 1 < ntile) preload((it + 1) << 6);   // hide LDG behind compute
        __syncthreads();

        if (s0 > wmax) continue;   // tile fully beyond this warp's causal range

        // ---- QK mma (single fp16) with nt-chunk causal skip ----
        float c[8][4];
        #pragma unroll
        for (int nt = 0; nt < 8; ++nt) { c[nt][0]=c[nt][1]=c[nt][2]=c[nt][3]=0.f; }

        const u32* qf0 = Qf + (16*w + g) * ATP_;
        const u32* qf1 = Qf + (16*w + g + 8) * ATP_;
        #pragma unroll
        for (int kk = 0; kk < 4; ++kk) {
            int cu = 8 * kk + tl;
            u32 a0 = qf0[cu], a1 = qf1[cu], a2 = qf0[cu+4], a3 = qf1[cu+4];
            #pragma unroll
            for (int nt = 0; nt < 8; ++nt) {
                if (s0 + 8 * nt <= wmax) {    // warp-uniform causal chunk skip
                    const u32* kp = Kf + (8*nt + g) * ATP_;
                    u32 b0 = kp[cu], b1 = kp[cu+4];
                    mma_f16(c[nt][0],c[nt][1],c[nt][2],c[nt][3], a0,a1,a2,a3, b0,b1);
                }
            }
        }

        // ---- softmax in registers ----
        float rm0 = -1e30f, rm1 = -1e30f;
        #pragma unroll
        for (int nt = 0; nt < 8; ++nt) {
            int sg = s0 + 8 * nt + 2 * tl;
            if (!(sg     <= r0g && sg     < len)) c[nt][0] = -1e30f;
            if (!(sg + 1 <= r0g && sg + 1 < len)) c[nt][1] = -1e30f;
            if (!(sg     <= r1g && sg     < len)) c[nt][2] = -1e30f;
            if (!(sg + 1 <= r1g && sg + 1 < len)) c[nt][3] = -1e30f;
            rm0 = fmaxf(rm0, fmaxf(c[nt][0], c[nt][1]));
            rm1 = fmaxf(rm1, fmaxf(c[nt][2], c[nt][3]));
        }
        rm0 = fmaxf(rm0, __shfl_xor_sync(0xFFFFFFFFu, rm0, 1));
        rm0 = fmaxf(rm0, __shfl_xor_sync(0xFFFFFFFFu, rm0, 2));
        rm1 = fmaxf(rm1, __shfl_xor_sync(0xFFFFFFFFu, rm1, 1));
        rm1 = fmaxf(rm1, __shfl_xor_sync(0xFFFFFFFFu, rm1, 2));

        float mn0 = fmaxf(mx0, rm0), mn1 = fmaxf(mx1, rm1);
        float alpha0 = __expf(mx0 - mn0), alpha1 = __expf(mx1 - mn1);
        mx0 = mn0; mx1 = mn1;

        u32 ph0[8], ph1[8];
        float s0s = 0.f, s1s = 0.f;
        #pragma unroll
        for (int nt = 0; nt < 8; ++nt) {
            float p00 = __expf(c[nt][0] - mn0), p01 = __expf(c[nt][1] - mn0);
            float p10 = __expf(c[nt][2] - mn1), p11 = __expf(c[nt][3] - mn1);
            s0s += p00 + p01; s1s += p10 + p11;
            ph0[nt] = cvt_f16x2(p00, p01);
            ph1[nt] = cvt_f16x2(p10, p11);
        }
        s0s += __shfl_xor_sync(0xFFFFFFFFu, s0s, 1);
        s0s += __shfl_xor_sync(0xFFFFFFFFu, s0s, 2);
        s1s += __shfl_xor_sync(0xFFFFFFFFu, s1s, 1);
        s1s += __shfl_xor_sync(0xFFFFFFFFu, s1s, 2);
        l0 = l0 * alpha0 + s0s;
        l1 = l1 * alpha1 + s1s;
        #pragma unroll
        for (int nt = 0; nt < 4; ++nt) {
            o[nt][0] *= alpha0; o[nt][1] *= alpha0;
            o[nt][2] *= alpha1; o[nt][3] *= alpha1;
        }

        // ---- PV mma: single fp16 per (nte,kk) ----
        #pragma unroll
        for (int nte = 0; nte < 4; ++nte) {
            const u32* vhp = Vth + (8*nte + g) * ATP_;
            #pragma unroll
            for (int kk = 0; kk < 4; ++kk) {
                int cu = 8 * kk + tl;
                u32 bh0 = vhp[cu], bh1 = vhp[cu+4];
                mma_f16(o[nte][0],o[nte][1],o[nte][2],o[nte][3],
                        ph0[2*kk], ph1[2*kk], ph0[2*kk+1], ph1[2*kk+1], bh0, bh1);
            }
        }
    }

    // Epilogue
    float i0 = 1.f / l0, i1 = 1.f / l1;
    #pragma unroll
    for (int nte = 0; nte < 4; ++nte) {
        int e = 8 * nte + 2 * tl;
        float2 v0 = make_float2(o[nte][0] * i0, o[nte][1] * i0);
        float2 v1 = make_float2(o[nte][2] * i1, o[nte][3] * i1);
        *(float2*)&out[(((size_t)b * Tv_ + r0g) * Mv_ + mm) * Pv_ + h * Ev_ + e] = v0;
        *(float2*)&out[(((size_t)b * Tv_ + r1g) * Mv_ + mm) * Pv_ + h * Ev_ + e] = v1;
    }
}

// ---------------------------------------------------------------------------
extern "C" void kernel_launch(void* const* d_in, const int* in_sizes, int n_in,
                              void* d_out, int out_size)
{
    const float* inp  = (const float*)d_in[0];
    const float* pos  = (const float*)d_in[1];
    const unsigned char* mask = (const unsigned char*)d_in[2];
    const float* Wq  = (const float*)d_in[3];
    const float* Bq  = (const float*)d_in[4];
    const float* Wk  = (const float*)d_in[5];
    const float* Bk  = (const float*)d_in[6];
    const float* Wv  = (const float*)d_in[7];
    const float* Bv  = (const float*)d_in[8];
    const float* Wqt = (const float*)d_in[9];
    const float* Bqt = (const float*)d_in[10];
    const float* Wkt = (const float*)d_in[11];
    const float* Bkt = (const float*)d_in[12];
    float* out = (float*)d_out;

    const float SCALE = 0.08838834764831845f; // 1 / (2*sqrt(32))

    const int PROJ_SMEM = (128 + 2 * 64) * PJP_ * 4;            // 69632 B
    const int ATTN_SMEM = (128 + 2*64 + 2*32) * ATP_ * 4;       // 46080 B
    cudaFuncSetAttribute(proj_kernel, cudaFuncAttributeMaxDynamicSharedMemorySize, PROJ_SMEM);
    cudaFuncSetAttribute(attn_kernel, cudaFuncAttributeMaxDynamicSharedMemorySize, ATTN_SMEM);

    dim3 pgrid(Mv_, BT_ / 128, 2);
    proj_kernel<<<pgrid, 256, PROJ_SMEM>>>(inp, pos,
        Wq, Bq, Wk, Bk, Wv, Bv, Wqt, Bqt, Wkt, Bkt, SCALE);

    dim3 agrid(Tv_ / 128, BMH_);
    attn_kernel<<<agrid, 256, ATTN_SMEM>>>(mask, out);
}